// round 5
// baseline (speedup 1.0000x reference)
#include <cuda_runtime.h>
#include <cuda_bf16.h>

#define Bn   4
#define Pn   900
#define Hn   8
#define DKn  64
#define DMn  512
#define PP2  (Pn*Pn)      // 810000
#define BHn  (Bn*Hn)      // 32
#define C1C  32

// ---- scratch (static device allocations; no runtime alloc) ----
__device__ float g_QP[Bn*Hn*Pn*DKn];        // 7.4 MB   [b,h,p,c]
__device__ float g_KP[Bn*Hn*Pn*DKn];        // 7.4 MB   [b,h,p,c]
__device__ float g_S [BHn*PP2];             // 103.7 MB scores -> attn -> conv2 out
__device__ float g_C1[Bn*C1C*PP2];          // 414.7 MB conv1 activations
__device__ int   g_IDX[BHn*Pn];             // argmax per (bh, key q)

// ============================================================
// K1: projection GEMM.  out[b,h,p,c] = sum_k A[(b*900+p), k] * W[(h*64+c), k] + bias
// M=3600, N=512, K=512. 64x64 tile, 256 thr, 4x4/thread.
// ============================================================
__global__ __launch_bounds__(256) void proj_kernel(const float* __restrict__ A,
                                                   const float* __restrict__ W,
                                                   const float* __restrict__ bias,
                                                   int which)
{
    float* out = which ? g_KP : g_QP;
    __shared__ float As[16][68];
    __shared__ float Bs[16][68];
    const int bm = blockIdx.y * 64;
    const int bn = blockIdx.x * 64;
    const int tid = threadIdx.x;
    const int lk = tid & 15, lm = tid >> 4;
    const int tx = tid & 15, ty = tid >> 4;
    float acc[4][4] = {};
    for (int k0 = 0; k0 < DMn; k0 += 16) {
        #pragma unroll
        for (int i = 0; i < 4; i++) {
            int m = bm + lm + i*16;
            As[lk][lm + i*16] = (m < Bn*Pn) ? A[m*DMn + k0 + lk] : 0.f;
            Bs[lk][lm + i*16] = W[(bn + lm + i*16)*DMn + k0 + lk];
        }
        __syncthreads();
        #pragma unroll
        for (int k = 0; k < 16; k++) {
            float a[4], b[4];
            #pragma unroll
            for (int i = 0; i < 4; i++) { a[i] = As[k][ty*4+i]; b[i] = Bs[k][tx*4+i]; }
            #pragma unroll
            for (int i = 0; i < 4; i++)
                #pragma unroll
                for (int j = 0; j < 4; j++) acc[i][j] += a[i]*b[j];
        }
        __syncthreads();
    }
    #pragma unroll
    for (int i = 0; i < 4; i++) {
        int m = bm + ty*4 + i;
        if (m >= Bn*Pn) continue;
        int b = m / Pn, p = m % Pn;
        #pragma unroll
        for (int j = 0; j < 4; j++) {
            int n = bn + tx*4 + j;
            out[((b*Hn + (n >> 6))*Pn + p)*DKn + (n & 63)] = acc[i][j] + bias[n];
        }
    }
}

// ============================================================
// K2: scores.  S[bh,p,q] = sum_c QP[bh,p,c] * KP[bh,q,c]
// 64x64 tile, K=64 single shot.
// ============================================================
__global__ __launch_bounds__(256) void scores_kernel()
{
    const int bh = blockIdx.z;
    const float* Q = g_QP + bh*Pn*DKn;
    const float* K = g_KP + bh*Pn*DKn;
    __shared__ float Qs[64][65];
    __shared__ float Ks[64][65];
    const int p0 = blockIdx.y*64, q0 = blockIdx.x*64;
    const int tid = threadIdx.x;
    #pragma unroll
    for (int i = 0; i < 16; i++) {
        int idx = tid + i*256;
        int r = idx >> 6, c = idx & 63;
        Qs[r][c] = (p0 + r < Pn) ? Q[(p0+r)*DKn + c] : 0.f;
        Ks[r][c] = (q0 + r < Pn) ? K[(q0+r)*DKn + c] : 0.f;
    }
    __syncthreads();
    const int tx = tid & 15, ty = tid >> 4;
    float acc[4][4] = {};
    #pragma unroll 16
    for (int k = 0; k < 64; k++) {
        float a[4], b[4];
        #pragma unroll
        for (int i = 0; i < 4; i++) { a[i] = Qs[ty*4+i][k]; b[i] = Ks[tx*4+i][k]; }
        #pragma unroll
        for (int i = 0; i < 4; i++)
            #pragma unroll
            for (int j = 0; j < 4; j++) acc[i][j] += a[i]*b[j];
    }
    float* Sb = g_S + bh*PP2;
    #pragma unroll
    for (int i = 0; i < 4; i++) {
        int p = p0 + ty*4 + i;
        if (p >= Pn) continue;
        #pragma unroll
        for (int j = 0; j < 4; j++) {
            int q = q0 + tx*4 + j;
            if (q < Pn) Sb[p*Pn + q] = acc[i][j];
        }
    }
}

// ============================================================
// K3: argmax over p (rows) per (bh, q column), first-occurrence ties.
// block: 64 q-columns x 4 row-groups of 225 rows.
// ============================================================
__global__ __launch_bounds__(256) void argmax_kernel()
{
    const int bh = blockIdx.y;
    const int tid = threadIdx.x;
    const int qi = (tid & 63) + blockIdx.x*64;
    const int rg = tid >> 6;
    const float* Sb = g_S + bh*PP2;
    float best = -1e30f; int bi = 0;
    if (qi < Pn) {
        int r0 = rg*225;
        #pragma unroll 5
        for (int p = r0; p < r0 + 225; p++) {
            float v = Sb[p*Pn + qi];
            if (v > best) { best = v; bi = p; }
        }
    }
    __shared__ float sv[256];
    __shared__ int   si[256];
    sv[tid] = best; si[tid] = bi;
    __syncthreads();
    if (rg == 0 && qi < Pn) {
        #pragma unroll
        for (int g = 1; g < 4; g++) {
            float v = sv[tid + g*64];
            int   ii = si[tid + g*64];
            if (v > best) { best = v; bi = ii; }   // later groups have larger p: tie keeps earlier
        }
        g_IDX[bh*Pn + qi] = bi;
    }
}

// ============================================================
// K4: gaussian modulation + scale + softmax (in-place on g_S rows).
// one block per (bh, p) row of 900.
// ============================================================
__global__ __launch_bounds__(256) void modsm_kernel()
{
    const int row = blockIdx.x;
    const int bh = row / Pn, p = row % Pn;
    float* Srow = g_S + bh*PP2 + p*Pn;
    const int* idxr = g_IDX + bh*Pn;
    const int ys = p / 30, xs = p % 30;
    const float ysc = -1.f + (2.f/29.f)*(float)ys;
    const float xsc = -1.f + (2.f/29.f)*(float)xs;
    const int tid = threadIdx.x;

    __shared__ float buf[Pn];
    __shared__ float red[256];

    float lmax = -1e30f;
    for (int q = tid; q < Pn; q += 256) {
        int id = idxr[q];
        float fy = (float)(id / 30);
        float fx = (float)(id - (id/30)*30);
        float dx = xsc - fx, dy = ysc - fy;
        float g = __expf(-(dx*dx + dy*dy) * 0.02f);       // 1/(2*sigma^2), sigma=5
        float v = g * Srow[q] * 0.125f;                   // / sqrt(64)
        buf[q] = v;
        lmax = fmaxf(lmax, v);
    }
    red[tid] = lmax; __syncthreads();
    for (int s = 128; s > 0; s >>= 1) { if (tid < s) red[tid] = fmaxf(red[tid], red[tid+s]); __syncthreads(); }
    const float m = red[0];
    __syncthreads();

    float lsum = 0.f;
    for (int q = tid; q < Pn; q += 256) {
        float e = __expf(buf[q] - m);
        buf[q] = e;
        lsum += e;
    }
    red[tid] = lsum; __syncthreads();
    for (int s = 128; s > 0; s >>= 1) { if (tid < s) red[tid] += red[tid+s]; __syncthreads(); }
    const float inv = 1.f / red[0];
    for (int q = tid; q < Pn; q += 256) Srow[q] = buf[q] * inv;
}

// ============================================================
// K5: conv1  (8 -> 32 ch, 3x3 SAME, relu).  input g_S, output g_C1.
// block = 16 rows x 64 cols tile; thread = 4 horiz pixels x 8 oc, 4 oc-groups.
// ============================================================
__global__ __launch_bounds__(256) void conv1_kernel(const float* __restrict__ w,
                                                    const float* __restrict__ bias)
{
    const int n  = blockIdx.z;
    const int x0 = blockIdx.x * 64;
    const int y0 = blockIdx.y * 16;
    __shared__ __align__(16) float sIn[8][18][68];
    __shared__ __align__(16) float sW[8*9*32];
    __shared__ float sB[32];
    const int tid = threadIdx.x;

    for (int i = tid; i < 2304; i += 256) {
        int oc = i & 31; int rest = i >> 5;
        int kk = rest % 9; int c = rest / 9;
        sW[(c*9 + kk)*32 + oc] = w[(oc*8 + c)*9 + kk];
    }
    if (tid < 32) sB[tid] = bias[tid];
    for (int c = 0; c < 8; c++) {
        const float* src = g_S + (size_t)(n*8 + c)*PP2;
        for (int i = tid; i < 18*68; i += 256) {
            int r = i / 68, col = i - r*68;
            int gy = y0 - 1 + r, gx = x0 - 1 + col;
            float v = 0.f;
            if (col < 66 && gy >= 0 && gy < Pn && gx >= 0 && gx < Pn) v = src[gy*Pn + gx];
            sIn[c][r][col] = v;
        }
    }
    __syncthreads();

    const int tx = tid & 15, ty = tid >> 4;
    const int lx = tx * 4;
    const int gy = y0 + ty;

    #pragma unroll 1
    for (int ocg = 0; ocg < 4; ocg++) {
        float acc[8][4] = {};
        #pragma unroll 2
        for (int c = 0; c < 8; c++) {
            #pragma unroll
            for (int ky = 0; ky < 3; ky++) {
                const float* rowp = &sIn[c][ty + ky][lx];
                float4 i4 = *(const float4*)rowp;
                float2 i2 = *(const float2*)(rowp + 4);
                float win[6] = {i4.x, i4.y, i4.z, i4.w, i2.x, i2.y};
                #pragma unroll
                for (int kx = 0; kx < 3; kx++) {
                    const float* wp = &sW[(c*9 + ky*3 + kx)*32 + ocg*8];
                    float4 wa = *(const float4*)wp;
                    float4 wb = *(const float4*)(wp + 4);
                    float wv[8] = {wa.x, wa.y, wa.z, wa.w, wb.x, wb.y, wb.z, wb.w};
                    #pragma unroll
                    for (int o = 0; o < 8; o++)
                        #pragma unroll
                        for (int px = 0; px < 4; px++)
                            acc[o][px] += wv[o] * win[px + kx];
                }
            }
        }
        if (gy < Pn) {
            #pragma unroll
            for (int o = 0; o < 8; o++) {
                int oc = ocg*8 + o;
                float bb = sB[oc];
                float* dst = g_C1 + (size_t)(n*C1C + oc)*PP2 + gy*Pn;
                #pragma unroll
                for (int px = 0; px < 4; px++) {
                    int gx = x0 + lx + px;
                    if (gx < Pn) dst[gx] = fmaxf(acc[o][px] + bb, 0.f);
                }
            }
        }
    }
}

// ============================================================
// K6: conv2  (32 -> 8 ch, 3x3 SAME, relu).  input g_C1, output g_S (reuse).
// input channels processed in 4 groups of 8 (smem refill), acc persists.
// ============================================================
__global__ __launch_bounds__(256) void conv2_kernel(const float* __restrict__ w,
                                                    const float* __restrict__ bias)
{
    const int n  = blockIdx.z;
    const int x0 = blockIdx.x * 64;
    const int y0 = blockIdx.y * 16;
    __shared__ __align__(16) float sIn[8][18][68];
    __shared__ __align__(16) float sW[32*9*8];
    __shared__ float sB[8];
    const int tid = threadIdx.x;

    for (int i = tid; i < 2304; i += 256) {
        int oc = i & 7; int rest = i >> 3;
        int kk = rest % 9; int c = rest / 9;
        sW[(c*9 + kk)*8 + oc] = w[(oc*32 + c)*9 + kk];
    }
    if (tid < 8) sB[tid] = bias[tid];

    const int tx = tid & 15, ty = tid >> 4;
    const int lx = tx * 4;
    const int gy = y0 + ty;
    float acc[8][4] = {};

    #pragma unroll 1
    for (int cg = 0; cg < 4; cg++) {
        __syncthreads();
        for (int lc = 0; lc < 8; lc++) {
            int c = cg*8 + lc;
            const float* src = g_C1 + (size_t)(n*C1C + c)*PP2;
            for (int i = tid; i < 18*68; i += 256) {
                int r = i / 68, col = i - r*68;
                int gyy = y0 - 1 + r, gxx = x0 - 1 + col;
                float v = 0.f;
                if (col < 66 && gyy >= 0 && gyy < Pn && gxx >= 0 && gxx < Pn) v = src[gyy*Pn + gxx];
                sIn[lc][r][col] = v;
            }
        }
        __syncthreads();
        #pragma unroll 2
        for (int lc = 0; lc < 8; lc++) {
            int c = cg*8 + lc;
            #pragma unroll
            for (int ky = 0; ky < 3; ky++) {
                const float* rowp = &sIn[lc][ty + ky][lx];
                float4 i4 = *(const float4*)rowp;
                float2 i2 = *(const float2*)(rowp + 4);
                float win[6] = {i4.x, i4.y, i4.z, i4.w, i2.x, i2.y};
                #pragma unroll
                for (int kx = 0; kx < 3; kx++) {
                    const float* wp = &sW[(c*9 + ky*3 + kx)*8];
                    float4 wa = *(const float4*)wp;
                    float4 wb = *(const float4*)(wp + 4);
                    float wv[8] = {wa.x, wa.y, wa.z, wa.w, wb.x, wb.y, wb.z, wb.w};
                    #pragma unroll
                    for (int o = 0; o < 8; o++)
                        #pragma unroll
                        for (int px = 0; px < 4; px++)
                            acc[o][px] += wv[o] * win[px + kx];
                }
            }
        }
    }
    if (gy < Pn) {
        #pragma unroll
        for (int o = 0; o < 8; o++) {
            float bb = sB[o];
            float* dst = g_S + (size_t)(n*Hn + o)*PP2 + gy*Pn;
            #pragma unroll
            for (int px = 0; px < 4; px++) {
                int gx = x0 + lx + px;
                if (gx < Pn) dst[gx] = fmaxf(acc[o][px] + bb, 0.f);
            }
        }
    }
}

// ============================================================
// K7: out[b,p] = mean_h sum_q attn2[b,h,p,q] * value[b,q]
// ============================================================
__global__ __launch_bounds__(256) void final_kernel(const float* __restrict__ value,
                                                    float* __restrict__ out)
{
    const int bp = blockIdx.x;
    const int b = bp / Pn, p = bp % Pn;
    const float* vrow = value + b*Pn;
    const int tid = threadIdx.x;
    float s = 0.f;
    #pragma unroll
    for (int h = 0; h < Hn; h++) {
        const float* ar = g_S + (size_t)(b*Hn + h)*PP2 + p*Pn;
        for (int q = tid; q < Pn; q += 256) s += ar[q] * vrow[q];
    }
    __shared__ float red[256];
    red[tid] = s; __syncthreads();
    for (int st = 128; st > 0; st >>= 1) { if (tid < st) red[tid] += red[tid+st]; __syncthreads(); }
    if (tid == 0) out[bp] = red[0] * 0.125f;
}

// ============================================================
extern "C" void kernel_launch(void* const* d_in, const int* in_sizes, int n_in,
                              void* d_out, int out_size)
{
    const float* query = (const float*)d_in[0];
    const float* key_t = (const float*)d_in[1];
    const float* value = (const float*)d_in[2];
    const float* Wq    = (const float*)d_in[3];
    const float* bq    = (const float*)d_in[4];
    const float* Wk    = (const float*)d_in[5];
    const float* bk    = (const float*)d_in[6];
    const float* c1w   = (const float*)d_in[7];
    const float* c1b   = (const float*)d_in[8];
    const float* c2w   = (const float*)d_in[9];
    const float* c2b   = (const float*)d_in[10];
    float* out = (float*)d_out;

    proj_kernel<<<dim3(8, 57), 256>>>(query, Wq, bq, 0);
    proj_kernel<<<dim3(8, 57), 256>>>(key_t, Wk, bk, 1);
    scores_kernel<<<dim3(15, 15, 32), 256>>>();
    argmax_kernel<<<dim3(15, 32), 256>>>();
    modsm_kernel<<<dim3(BHn*Pn), 256>>>();
    conv1_kernel<<<dim3(15, 57, 4), 256>>>(c1w, c1b);
    conv2_kernel<<<dim3(15, 57, 4), 256>>>(c2w, c2b);
    final_kernel<<<dim3(Bn*Pn), 256>>>(value, out);
}

// round 6
// speedup vs baseline: 1.1764x; 1.1764x over previous
#include <cuda_runtime.h>
#include <cuda_bf16.h>

#define Bn   4
#define Pn   900
#define Hn   8
#define DKn  64
#define DMn  512
#define PP2  (Pn*Pn)      // 810000
#define BHn  (Bn*Hn)      // 32
#define C1C  32

typedef unsigned long long u64_t;

// packed dual-fp32 FMA (Blackwell f32x2 pipe; not emitted by ptxas from C++)
__device__ __forceinline__ u64_t fma2(u64_t a, u64_t b, u64_t c) {
    u64_t d;
    asm("fma.rn.f32x2 %0, %1, %2, %3;" : "=l"(d) : "l"(a), "l"(b), "l"(c));
    return d;
}
__device__ __forceinline__ u64_t dup2f(float v) {
    u64_t d;
    asm("mov.b64 %0, {%1, %1};" : "=l"(d) : "r"(__float_as_uint(v)));
    return d;
}
__device__ __forceinline__ float2 unp2(u64_t v) {
    unsigned lo, hi;
    asm("mov.b64 {%0, %1}, %2;" : "=r"(lo), "=r"(hi) : "l"(v));
    float2 r; r.x = __uint_as_float(lo); r.y = __uint_as_float(hi);
    return r;
}

// ---- scratch (static device allocations; no runtime alloc) ----
__device__ float g_QP[Bn*Hn*Pn*DKn];        // [b,h,p,c]
__device__ float g_KP[Bn*Hn*Pn*DKn];        // [b,h,p,c]
__device__ float g_S [BHn*PP2];             // scores -> attn -> conv2 out
__device__ float g_C1[Bn*C1C*PP2];          // conv1 activations
__device__ int   g_IDX[BHn*Pn];             // argmax per (bh, key q)

// ============================================================
// K1: projection GEMM.  out[b,h,p,c] = sum_k A[m,k] * W[n,k] + bias
// M=3600, N=512, K=512. 64x64 tile, 256 thr, 4x4/thread (f32x2 over n).
// ============================================================
__global__ __launch_bounds__(256) void proj_kernel(const float* __restrict__ A,
                                                   const float* __restrict__ W,
                                                   const float* __restrict__ bias,
                                                   int which)
{
    float* out = which ? g_KP : g_QP;
    __shared__ __align__(16) float As[16][68];
    __shared__ __align__(16) float Bs[16][68];
    const int bm = blockIdx.y * 64;
    const int bn = blockIdx.x * 64;
    const int tid = threadIdx.x;
    const int lk = tid & 15, lm = tid >> 4;
    const int tx = tid & 15, ty = tid >> 4;
    u64_t acc2[4][2] = {};
    for (int k0 = 0; k0 < DMn; k0 += 16) {
        #pragma unroll
        for (int i = 0; i < 4; i++) {
            int m = bm + lm + i*16;
            As[lk][lm + i*16] = (m < Bn*Pn) ? A[m*DMn + k0 + lk] : 0.f;
            Bs[lk][lm + i*16] = W[(bn + lm + i*16)*DMn + k0 + lk];
        }
        __syncthreads();
        #pragma unroll
        for (int k = 0; k < 16; k++) {
            float4 av = *(const float4*)&As[k][ty*4];
            const u64_t* bp = (const u64_t*)&Bs[k][tx*4];
            u64_t b01 = bp[0], b23 = bp[1];
            u64_t a_[4] = {dup2f(av.x), dup2f(av.y), dup2f(av.z), dup2f(av.w)};
            #pragma unroll
            for (int i = 0; i < 4; i++) {
                acc2[i][0] = fma2(a_[i], b01, acc2[i][0]);
                acc2[i][1] = fma2(a_[i], b23, acc2[i][1]);
            }
        }
        __syncthreads();
    }
    #pragma unroll
    for (int i = 0; i < 4; i++) {
        int m = bm + ty*4 + i;
        if (m >= Bn*Pn) continue;
        int b = m / Pn, p = m % Pn;
        #pragma unroll
        for (int jp = 0; jp < 2; jp++) {
            float2 v = unp2(acc2[i][jp]);
            int n0 = bn + tx*4 + jp*2;
            out[((b*Hn + (n0 >> 6))*Pn + p)*DKn + (n0 & 63)]       = v.x + bias[n0];
            out[((b*Hn + ((n0+1) >> 6))*Pn + p)*DKn + ((n0+1) & 63)] = v.y + bias[n0+1];
        }
    }
}

// ============================================================
// K2: scores.  S[bh,p,q] = sum_c QP[bh,p,c] * KP[bh,q,c]
// 64x64 tile, K=64. smem transposed [k][row] for f32x2 B pairs.
// ============================================================
__global__ __launch_bounds__(256) void scores_kernel()
{
    const int bh = blockIdx.z;
    const float* Q = g_QP + bh*Pn*DKn;
    const float* K = g_KP + bh*Pn*DKn;
    __shared__ __align__(16) float Qs[64][68];   // [k][row]
    __shared__ __align__(16) float Ks[64][68];   // [k][row]
    const int p0 = blockIdx.y*64, q0 = blockIdx.x*64;
    const int tid = threadIdx.x;
    #pragma unroll
    for (int i = 0; i < 16; i++) {
        int idx = tid + i*256;
        int r = idx >> 6, c = idx & 63;
        Qs[c][r] = (p0 + r < Pn) ? Q[(p0+r)*DKn + c] : 0.f;
        Ks[c][r] = (q0 + r < Pn) ? K[(q0+r)*DKn + c] : 0.f;
    }
    __syncthreads();
    const int tx = tid & 15, ty = tid >> 4;
    u64_t acc2[4][2] = {};
    #pragma unroll 8
    for (int k = 0; k < 64; k++) {
        float4 av = *(const float4*)&Qs[k][ty*4];
        const u64_t* bp = (const u64_t*)&Ks[k][tx*4];
        u64_t b01 = bp[0], b23 = bp[1];
        u64_t a_[4] = {dup2f(av.x), dup2f(av.y), dup2f(av.z), dup2f(av.w)};
        #pragma unroll
        for (int i = 0; i < 4; i++) {
            acc2[i][0] = fma2(a_[i], b01, acc2[i][0]);
            acc2[i][1] = fma2(a_[i], b23, acc2[i][1]);
        }
    }
    float* Sb = g_S + bh*PP2;
    #pragma unroll
    for (int i = 0; i < 4; i++) {
        int p = p0 + ty*4 + i;
        if (p >= Pn) continue;
        #pragma unroll
        for (int jp = 0; jp < 2; jp++) {
            float2 v = unp2(acc2[i][jp]);
            int q = q0 + tx*4 + jp*2;
            if (q < Pn)     Sb[p*Pn + q]     = v.x;
            if (q + 1 < Pn) Sb[p*Pn + q + 1] = v.y;
        }
    }
}

// ============================================================
// K3: argmax over p (rows) per (bh, q column), first-occurrence ties.
// ============================================================
__global__ __launch_bounds__(256) void argmax_kernel()
{
    const int bh = blockIdx.y;
    const int tid = threadIdx.x;
    const int qi = (tid & 63) + blockIdx.x*64;
    const int rg = tid >> 6;
    const float* Sb = g_S + bh*PP2;
    float best = -1e30f; int bi = 0;
    if (qi < Pn) {
        int r0 = rg*225;
        #pragma unroll 5
        for (int p = r0; p < r0 + 225; p++) {
            float v = Sb[p*Pn + qi];
            if (v > best) { best = v; bi = p; }
        }
    }
    __shared__ float sv[256];
    __shared__ int   si[256];
    sv[tid] = best; si[tid] = bi;
    __syncthreads();
    if (rg == 0 && qi < Pn) {
        #pragma unroll
        for (int g = 1; g < 4; g++) {
            float v = sv[tid + g*64];
            int   ii = si[tid + g*64];
            if (v > best) { best = v; bi = ii; }   // later groups have larger p: tie keeps earlier
        }
        g_IDX[bh*Pn + qi] = bi;
    }
}

// ============================================================
// K4: gaussian modulation + scale + softmax (in-place on g_S rows).
// ============================================================
__global__ __launch_bounds__(256) void modsm_kernel()
{
    const int row = blockIdx.x;
    const int bh = row / Pn, p = row % Pn;
    float* Srow = g_S + bh*PP2 + p*Pn;
    const int* idxr = g_IDX + bh*Pn;
    const int ys = p / 30, xs = p % 30;
    const float ysc = -1.f + (2.f/29.f)*(float)ys;
    const float xsc = -1.f + (2.f/29.f)*(float)xs;
    const int tid = threadIdx.x;

    __shared__ float buf[Pn];
    __shared__ float red[256];

    float lmax = -1e30f;
    for (int q = tid; q < Pn; q += 256) {
        int id = idxr[q];
        float fy = (float)(id / 30);
        float fx = (float)(id - (id/30)*30);
        float dx = xsc - fx, dy = ysc - fy;
        float g = __expf(-(dx*dx + dy*dy) * 0.02f);       // 1/(2*sigma^2), sigma=5
        float v = g * Srow[q] * 0.125f;                   // / sqrt(64)
        buf[q] = v;
        lmax = fmaxf(lmax, v);
    }
    red[tid] = lmax; __syncthreads();
    for (int s = 128; s > 0; s >>= 1) { if (tid < s) red[tid] = fmaxf(red[tid], red[tid+s]); __syncthreads(); }
    const float m = red[0];
    __syncthreads();

    float lsum = 0.f;
    for (int q = tid; q < Pn; q += 256) {
        float e = __expf(buf[q] - m);
        buf[q] = e;
        lsum += e;
    }
    red[tid] = lsum; __syncthreads();
    for (int s = 128; s > 0; s >>= 1) { if (tid < s) red[tid] += red[tid+s]; __syncthreads(); }
    const float inv = 1.f / red[0];
    for (int q = tid; q < Pn; q += 256) Srow[q] = buf[q] * inv;
}

// ============================================================
// K5: conv1  (8 -> 32 ch, 3x3 SAME, relu).  input g_S, output g_C1.
// thread = 4 px x 8 oc (as 4 oc-pairs via f32x2), 4 oc-groups.
// ============================================================
__global__ __launch_bounds__(256) void conv1_kernel(const float* __restrict__ w,
                                                    const float* __restrict__ bias)
{
    const int n  = blockIdx.z;
    const int x0 = blockIdx.x * 64;
    const int y0 = blockIdx.y * 16;
    __shared__ __align__(16) float sIn[8][18][68];
    __shared__ __align__(16) float sW[8*9*32];
    __shared__ float sB[32];
    const int tid = threadIdx.x;

    for (int i = tid; i < 2304; i += 256) {
        int oc = i & 31; int rest = i >> 5;
        int kk = rest % 9; int c = rest / 9;
        sW[(c*9 + kk)*32 + oc] = w[(oc*8 + c)*9 + kk];
    }
    if (tid < 32) sB[tid] = bias[tid];
    for (int c = 0; c < 8; c++) {
        const float* src = g_S + (size_t)(n*8 + c)*PP2;
        for (int i = tid; i < 18*68; i += 256) {
            int r = i / 68, col = i - r*68;
            int gy = y0 - 1 + r, gx = x0 - 1 + col;
            float v = 0.f;
            if (col < 66 && gy >= 0 && gy < Pn && gx >= 0 && gx < Pn) v = src[gy*Pn + gx];
            sIn[c][r][col] = v;
        }
    }
    __syncthreads();

    const int tx = tid & 15, ty = tid >> 4;
    const int lx = tx * 4;
    const int gy = y0 + ty;

    #pragma unroll 1
    for (int ocg = 0; ocg < 4; ocg++) {
        u64_t acc2[4][4] = {};
        #pragma unroll 2
        for (int c = 0; c < 8; c++) {
            #pragma unroll
            for (int ky = 0; ky < 3; ky++) {
                const float* rowp = &sIn[c][ty + ky][lx];
                float4 i4 = *(const float4*)rowp;
                float2 i2 = *(const float2*)(rowp + 4);
                u64_t wd[6] = {dup2f(i4.x), dup2f(i4.y), dup2f(i4.z),
                               dup2f(i4.w), dup2f(i2.x), dup2f(i2.y)};
                #pragma unroll
                for (int kx = 0; kx < 3; kx++) {
                    const u64_t* wp = (const u64_t*)&sW[(c*9 + ky*3 + kx)*32 + ocg*8];
                    u64_t w0 = wp[0], w1 = wp[1], w2 = wp[2], w3 = wp[3];
                    #pragma unroll
                    for (int px = 0; px < 4; px++) {
                        acc2[0][px] = fma2(w0, wd[px + kx], acc2[0][px]);
                        acc2[1][px] = fma2(w1, wd[px + kx], acc2[1][px]);
                        acc2[2][px] = fma2(w2, wd[px + kx], acc2[2][px]);
                        acc2[3][px] = fma2(w3, wd[px + kx], acc2[3][px]);
                    }
                }
            }
        }
        if (gy < Pn) {
            #pragma unroll
            for (int op = 0; op < 4; op++) {
                int oc0 = ocg*8 + op*2;
                float b0 = sB[oc0], b1 = sB[oc0 + 1];
                float* dst0 = g_C1 + (size_t)(n*C1C + oc0)*PP2 + gy*Pn;
                float* dst1 = dst0 + PP2;
                #pragma unroll
                for (int px = 0; px < 4; px++) {
                    int gx = x0 + lx + px;
                    if (gx < Pn) {
                        float2 v = unp2(acc2[op][px]);
                        dst0[gx] = fmaxf(v.x + b0, 0.f);
                        dst1[gx] = fmaxf(v.y + b1, 0.f);
                    }
                }
            }
        }
    }
}

// ============================================================
// K6: conv2  (32 -> 8 ch, 3x3 SAME, relu).  input g_C1, output g_S.
// input channels in 4 groups of 8 (smem refill), f32x2 oc pairs.
// ============================================================
__global__ __launch_bounds__(256) void conv2_kernel(const float* __restrict__ w,
                                                    const float* __restrict__ bias)
{
    const int n  = blockIdx.z;
    const int x0 = blockIdx.x * 64;
    const int y0 = blockIdx.y * 16;
    __shared__ __align__(16) float sIn[8][18][68];
    __shared__ __align__(16) float sW[32*9*8];
    __shared__ float sB[8];
    const int tid = threadIdx.x;

    for (int i = tid; i < 2304; i += 256) {
        int oc = i & 7; int rest = i >> 3;
        int kk = rest % 9; int c = rest / 9;
        sW[(c*9 + kk)*8 + oc] = w[(oc*32 + c)*9 + kk];
    }
    if (tid < 8) sB[tid] = bias[tid];

    const int tx = tid & 15, ty = tid >> 4;
    const int lx = tx * 4;
    const int gy = y0 + ty;
    u64_t acc2[4][4] = {};

    #pragma unroll 1
    for (int cg = 0; cg < 4; cg++) {
        __syncthreads();
        for (int lc = 0; lc < 8; lc++) {
            int c = cg*8 + lc;
            const float* src = g_C1 + (size_t)(n*C1C + c)*PP2;
            for (int i = tid; i < 18*68; i += 256) {
                int r = i / 68, col = i - r*68;
                int gyy = y0 - 1 + r, gxx = x0 - 1 + col;
                float v = 0.f;
                if (col < 66 && gyy >= 0 && gyy < Pn && gxx >= 0 && gxx < Pn) v = src[gyy*Pn + gxx];
                sIn[lc][r][col] = v;
            }
        }
        __syncthreads();
        #pragma unroll 2
        for (int lc = 0; lc < 8; lc++) {
            int c = cg*8 + lc;
            #pragma unroll
            for (int ky = 0; ky < 3; ky++) {
                const float* rowp = &sIn[lc][ty + ky][lx];
                float4 i4 = *(const float4*)rowp;
                float2 i2 = *(const float2*)(rowp + 4);
                u64_t wd[6] = {dup2f(i4.x), dup2f(i4.y), dup2f(i4.z),
                               dup2f(i4.w), dup2f(i2.x), dup2f(i2.y)};
                #pragma unroll
                for (int kx = 0; kx < 3; kx++) {
                    const u64_t* wp = (const u64_t*)&sW[(c*9 + ky*3 + kx)*8];
                    u64_t w0 = wp[0], w1 = wp[1], w2 = wp[2], w3 = wp[3];
                    #pragma unroll
                    for (int px = 0; px < 4; px++) {
                        acc2[0][px] = fma2(w0, wd[px + kx], acc2[0][px]);
                        acc2[1][px] = fma2(w1, wd[px + kx], acc2[1][px]);
                        acc2[2][px] = fma2(w2, wd[px + kx], acc2[2][px]);
                        acc2[3][px] = fma2(w3, wd[px + kx], acc2[3][px]);
                    }
                }
            }
        }
    }
    if (gy < Pn) {
        #pragma unroll
        for (int op = 0; op < 4; op++) {
            int oc0 = op*2;
            float b0 = sB[oc0], b1 = sB[oc0 + 1];
            float* dst0 = g_S + (size_t)(n*Hn + oc0)*PP2 + gy*Pn;
            float* dst1 = dst0 + PP2;
            #pragma unroll
            for (int px = 0; px < 4; px++) {
                int gx = x0 + lx + px;
                if (gx < Pn) {
                    float2 v = unp2(acc2[op][px]);
                    dst0[gx] = fmaxf(v.x + b0, 0.f);
                    dst1[gx] = fmaxf(v.y + b1, 0.f);
                }
            }
        }
    }
}

// ============================================================
// K7: out[b,p] = mean_h sum_q attn2[b,h,p,q] * value[b,q]
// ============================================================
__global__ __launch_bounds__(256) void final_kernel(const float* __restrict__ value,
                                                    float* __restrict__ out)
{
    const int bp = blockIdx.x;
    const int b = bp / Pn, p = bp % Pn;
    const float* vrow = value + b*Pn;
    const int tid = threadIdx.x;
    float s = 0.f;
    #pragma unroll
    for (int h = 0; h < Hn; h++) {
        const float* ar = g_S + (size_t)(b*Hn + h)*PP2 + p*Pn;
        for (int q = tid; q < Pn; q += 256) s += ar[q] * vrow[q];
    }
    __shared__ float red[256];
    red[tid] = s; __syncthreads();
    for (int st = 128; st > 0; st >>= 1) { if (tid < st) red[tid] += red[tid+st]; __syncthreads(); }
    if (tid == 0) out[bp] = red[0] * 0.125f;
}

// ============================================================
extern "C" void kernel_launch(void* const* d_in, const int* in_sizes, int n_in,
                              void* d_out, int out_size)
{
    const float* query = (const float*)d_in[0];
    const float* key_t = (const float*)d_in[1];
    const float* value = (const float*)d_in[2];
    const float* Wq    = (const float*)d_in[3];
    const float* bq    = (const float*)d_in[4];
    const float* Wk    = (const float*)d_in[5];
    const float* bk    = (const float*)d_in[6];
    const float* c1w   = (const float*)d_in[7];
    const float* c1b   = (const float*)d_in[8];
    const float* c2w   = (const float*)d_in[9];
    const float* c2b   = (const float*)d_in[10];
    float* out = (float*)d_out;

    proj_kernel<<<dim3(8, 57), 256>>>(query, Wq, bq, 0);
    proj_kernel<<<dim3(8, 57), 256>>>(key_t, Wk, bk, 1);
    scores_kernel<<<dim3(15, 15, 32), 256>>>();
    argmax_kernel<<<dim3(15, 32), 256>>>();
    modsm_kernel<<<dim3(BHn*Pn), 256>>>();
    conv1_kernel<<<dim3(15, 57, 4), 256>>>(c1w, c1b);
    conv2_kernel<<<dim3(15, 57, 4), 256>>>(c2w, c2b);
    final_kernel<<<dim3(Bn*Pn), 256>>>(value, out);
}

// round 7
// speedup vs baseline: 1.6029x; 1.3626x over previous
#include <cuda_runtime.h>
#include <cuda_bf16.h>

#define Bn   4
#define Pn   900
#define Hn   8
#define DKn  64
#define DMn  512
#define PP2  (Pn*Pn)      // 810000
#define BHn  (Bn*Hn)      // 32
#define C1C  32

typedef unsigned long long u64_t;

// ---- packed dual-fp32 FMA helpers (Blackwell f32x2 pipe) ----
__device__ __forceinline__ u64_t fma2(u64_t a, u64_t b, u64_t c) {
    u64_t d;
    asm("fma.rn.f32x2 %0, %1, %2, %3;" : "=l"(d) : "l"(a), "l"(b), "l"(c));
    return d;
}
__device__ __forceinline__ u64_t dup2f(float v) {
    u64_t d;
    asm("mov.b64 %0, {%1, %1};" : "=l"(d) : "r"(__float_as_uint(v)));
    return d;
}
__device__ __forceinline__ float2 unp2(u64_t v) {
    unsigned lo, hi;
    asm("mov.b64 {%0, %1}, %2;" : "=r"(lo), "=r"(hi) : "l"(v));
    float2 r; r.x = __uint_as_float(lo); r.y = __uint_as_float(hi);
    return r;
}

// ---- tf32 tensor-core helpers ----
__device__ __forceinline__ unsigned tf32_of(float f) {
    unsigned u;
    asm("cvt.rna.tf32.f32 %0, %1;" : "=r"(u) : "f"(f));
    return u;
}
__device__ __forceinline__ void mma_tf32(float* c, const unsigned* a, const unsigned* b) {
    asm("mma.sync.aligned.m16n8k8.row.col.f32.tf32.tf32.f32 "
        "{%0,%1,%2,%3}, {%4,%5,%6,%7}, {%8,%9}, {%0,%1,%2,%3};"
        : "+f"(c[0]), "+f"(c[1]), "+f"(c[2]), "+f"(c[3])
        : "r"(a[0]), "r"(a[1]), "r"(a[2]), "r"(a[3]), "r"(b[0]), "r"(b[1]));
}

// ---- scratch (static device allocations; no runtime alloc) ----
__device__ float g_QP[Bn*Hn*Pn*DKn];        // [b,h,p,c]
__device__ float g_KP[Bn*Hn*Pn*DKn];        // [b,h,p,c]
__device__ float g_S [BHn*PP2];             // scores -> attn -> conv2 out
__device__ float g_C1[Bn*C1C*PP2];          // conv1 activations
__device__ int   g_IDX[BHn*Pn];             // argmax per (bh, key q)

// ============================================================
// K1: projection GEMM (fp32 f32x2 — feeds argmax-sensitive path)
// ============================================================
__global__ __launch_bounds__(256) void proj_kernel(const float* __restrict__ A,
                                                   const float* __restrict__ W,
                                                   const float* __restrict__ bias,
                                                   int which)
{
    float* out = which ? g_KP : g_QP;
    __shared__ __align__(16) float As[16][68];
    __shared__ __align__(16) float Bs[16][68];
    const int bm = blockIdx.y * 64;
    const int bn = blockIdx.x * 64;
    const int tid = threadIdx.x;
    const int lk = tid & 15, lm = tid >> 4;
    const int tx = tid & 15, ty = tid >> 4;
    u64_t acc2[4][2] = {};
    for (int k0 = 0; k0 < DMn; k0 += 16) {
        #pragma unroll
        for (int i = 0; i < 4; i++) {
            int m = bm + lm + i*16;
            As[lk][lm + i*16] = (m < Bn*Pn) ? A[m*DMn + k0 + lk] : 0.f;
            Bs[lk][lm + i*16] = W[(bn + lm + i*16)*DMn + k0 + lk];
        }
        __syncthreads();
        #pragma unroll
        for (int k = 0; k < 16; k++) {
            float4 av = *(const float4*)&As[k][ty*4];
            const u64_t* bp = (const u64_t*)&Bs[k][tx*4];
            u64_t b01 = bp[0], b23 = bp[1];
            u64_t a_[4] = {dup2f(av.x), dup2f(av.y), dup2f(av.z), dup2f(av.w)};
            #pragma unroll
            for (int i = 0; i < 4; i++) {
                acc2[i][0] = fma2(a_[i], b01, acc2[i][0]);
                acc2[i][1] = fma2(a_[i], b23, acc2[i][1]);
            }
        }
        __syncthreads();
    }
    #pragma unroll
    for (int i = 0; i < 4; i++) {
        int m = bm + ty*4 + i;
        if (m >= Bn*Pn) continue;
        int b = m / Pn, p = m % Pn;
        #pragma unroll
        for (int jp = 0; jp < 2; jp++) {
            float2 v = unp2(acc2[i][jp]);
            int n0 = bn + tx*4 + jp*2;
            out[((b*Hn + (n0 >> 6))*Pn + p)*DKn + (n0 & 63)]       = v.x + bias[n0];
            out[((b*Hn + ((n0+1) >> 6))*Pn + p)*DKn + ((n0+1) & 63)] = v.y + bias[n0+1];
        }
    }
}

// ============================================================
// K2: scores (fp32 f32x2)
// ============================================================
__global__ __launch_bounds__(256) void scores_kernel()
{
    const int bh = blockIdx.z;
    const float* Q = g_QP + bh*Pn*DKn;
    const float* K = g_KP + bh*Pn*DKn;
    __shared__ __align__(16) float Qs[64][68];   // [k][row]
    __shared__ __align__(16) float Ks[64][68];   // [k][row]
    const int p0 = blockIdx.y*64, q0 = blockIdx.x*64;
    const int tid = threadIdx.x;
    #pragma unroll
    for (int i = 0; i < 16; i++) {
        int idx = tid + i*256;
        int r = idx >> 6, c = idx & 63;
        Qs[c][r] = (p0 + r < Pn) ? Q[(p0+r)*DKn + c] : 0.f;
        Ks[c][r] = (q0 + r < Pn) ? K[(q0+r)*DKn + c] : 0.f;
    }
    __syncthreads();
    const int tx = tid & 15, ty = tid >> 4;
    u64_t acc2[4][2] = {};
    #pragma unroll 8
    for (int k = 0; k < 64; k++) {
        float4 av = *(const float4*)&Qs[k][ty*4];
        const u64_t* bp = (const u64_t*)&Ks[k][tx*4];
        u64_t b01 = bp[0], b23 = bp[1];
        u64_t a_[4] = {dup2f(av.x), dup2f(av.y), dup2f(av.z), dup2f(av.w)};
        #pragma unroll
        for (int i = 0; i < 4; i++) {
            acc2[i][0] = fma2(a_[i], b01, acc2[i][0]);
            acc2[i][1] = fma2(a_[i], b23, acc2[i][1]);
        }
    }
    float* Sb = g_S + bh*PP2;
    #pragma unroll
    for (int i = 0; i < 4; i++) {
        int p = p0 + ty*4 + i;
        if (p >= Pn) continue;
        #pragma unroll
        for (int jp = 0; jp < 2; jp++) {
            float2 v = unp2(acc2[i][jp]);
            int q = q0 + tx*4 + jp*2;
            if (q < Pn)     Sb[p*Pn + q]     = v.x;
            if (q + 1 < Pn) Sb[p*Pn + q + 1] = v.y;
        }
    }
}

// ============================================================
// K3: argmax over p per (bh, q), first-occurrence ties.
// ============================================================
__global__ __launch_bounds__(256) void argmax_kernel()
{
    const int bh = blockIdx.y;
    const int tid = threadIdx.x;
    const int qi = (tid & 63) + blockIdx.x*64;
    const int rg = tid >> 6;
    const float* Sb = g_S + bh*PP2;
    float best = -1e30f; int bi = 0;
    if (qi < Pn) {
        int r0 = rg*225;
        #pragma unroll 5
        for (int p = r0; p < r0 + 225; p++) {
            float v = Sb[p*Pn + qi];
            if (v > best) { best = v; bi = p; }
        }
    }
    __shared__ float sv[256];
    __shared__ int   si[256];
    sv[tid] = best; si[tid] = bi;
    __syncthreads();
    if (rg == 0 && qi < Pn) {
        #pragma unroll
        for (int g = 1; g < 4; g++) {
            float v = sv[tid + g*64];
            int   ii = si[tid + g*64];
            if (v > best) { best = v; bi = ii; }
        }
        g_IDX[bh*Pn + qi] = bi;
    }
}

// ============================================================
// K4: gaussian modulation + scale + softmax
// ============================================================
__global__ __launch_bounds__(256) void modsm_kernel()
{
    const int row = blockIdx.x;
    const int bh = row / Pn, p = row % Pn;
    float* Srow = g_S + bh*PP2 + p*Pn;
    const int* idxr = g_IDX + bh*Pn;
    const int ys = p / 30, xs = p % 30;
    const float ysc = -1.f + (2.f/29.f)*(float)ys;
    const float xsc = -1.f + (2.f/29.f)*(float)xs;
    const int tid = threadIdx.x;

    __shared__ float buf[Pn];
    __shared__ float red[256];

    float lmax = -1e30f;
    for (int q = tid; q < Pn; q += 256) {
        int id = idxr[q];
        float fy = (float)(id / 30);
        float fx = (float)(id - (id/30)*30);
        float dx = xsc - fx, dy = ysc - fy;
        float g = __expf(-(dx*dx + dy*dy) * 0.02f);
        float v = g * Srow[q] * 0.125f;
        buf[q] = v;
        lmax = fmaxf(lmax, v);
    }
    red[tid] = lmax; __syncthreads();
    for (int s = 128; s > 0; s >>= 1) { if (tid < s) red[tid] = fmaxf(red[tid], red[tid+s]); __syncthreads(); }
    const float m = red[0];
    __syncthreads();

    float lsum = 0.f;
    for (int q = tid; q < Pn; q += 256) {
        float e = __expf(buf[q] - m);
        buf[q] = e;
        lsum += e;
    }
    red[tid] = lsum; __syncthreads();
    for (int s = 128; s > 0; s >>= 1) { if (tid < s) red[tid] += red[tid+s]; __syncthreads(); }
    const float inv = 1.f / red[0];
    for (int q = tid; q < Pn; q += 256) Srow[q] = buf[q] * inv;
}

// ============================================================
// K5: conv1 (8 -> 32 ch, 3x3 SAME, relu) via tf32 mma.m16n8k8.
// block: 64x16 px tile, 8 warps, warp-tile = 16 px (x-run).
// smem input interleaved [row][col][ic], ic-stride padded to 9.
// ============================================================
__global__ __launch_bounds__(256) void conv1_kernel(const float* __restrict__ w,
                                                    const float* __restrict__ bias)
{
    const int n  = blockIdx.z;
    const int x0 = blockIdx.x * 64;
    const int y0 = blockIdx.y * 16;
    __shared__ unsigned sIn[18*68*9];   // tf32 bits, 44 KB
    __shared__ float sB[32];
    const int tid  = threadIdx.x;
    const int lane = tid & 31, wid = tid >> 5;
    const int qr = lane >> 2, icb = lane & 3;

    // B fragments in registers: [shift][ocg][2]
    unsigned bf[9][4][2];
    #pragma unroll
    for (int s = 0; s < 9; s++)
        #pragma unroll
        for (int g = 0; g < 4; g++) {
            int oc = g*8 + qr;
            bf[s][g][0] = tf32_of(w[(oc*8 + icb)*9 + s]);
            bf[s][g][1] = tf32_of(w[(oc*8 + icb + 4)*9 + s]);
        }
    if (tid < 32) sB[tid] = bias[tid];

    // stage input tile (with halo) interleaved + tf32-converted
    for (int i = tid; i < 18*68; i += 256) {
        int r = i / 68, c = i - r*68;
        int gy = y0 - 1 + r, gx = x0 - 1 + c;
        bool ok = (c < 66) && gy >= 0 && gy < Pn && gx >= 0 && gx < Pn;
        const float* base = g_S + (size_t)(n*8)*PP2 + (size_t)gy*Pn + gx;
        #pragma unroll
        for (int ic = 0; ic < 8; ic++) {
            float v = ok ? base[(size_t)ic*PP2] : 0.f;
            sIn[i*9 + ic] = tf32_of(v);
        }
    }
    __syncthreads();

    #pragma unroll 1
    for (int j = 0; j < 8; j++) {
        int t = wid*8 + j;          // 0..63
        int ty = t >> 2;            // 0..15
        int xs = (t & 3) * 16;      // x-segment
        float acc[4][4] = {};
        #pragma unroll
        for (int ky = 0; ky < 3; ky++) {
            #pragma unroll
            for (int kx = 0; kx < 3; kx++) {
                int rb = (ty + ky)*68 + xs + kx;
                unsigned a[4];
                a[0] = sIn[(rb + qr)*9 + icb];
                a[1] = sIn[(rb + qr + 8)*9 + icb];
                a[2] = sIn[(rb + qr)*9 + icb + 4];
                a[3] = sIn[(rb + qr + 8)*9 + icb + 4];
                int s = ky*3 + kx;
                #pragma unroll
                for (int g = 0; g < 4; g++) mma_tf32(acc[g], a, bf[s][g]);
            }
        }
        int y = y0 + ty;
        if (y < Pn) {
            int xA = x0 + xs + qr, xB = xA + 8;
            #pragma unroll
            for (int g = 0; g < 4; g++) {
                int oc = g*8 + 2*icb;
                float b0 = sB[oc], b1 = sB[oc+1];
                float* p0 = g_C1 + (size_t)(n*C1C + oc)*PP2 + (size_t)y*Pn;
                float* p1 = p0 + PP2;
                if (xA < Pn) { p0[xA] = fmaxf(acc[g][0] + b0, 0.f);
                               p1[xA] = fmaxf(acc[g][1] + b1, 0.f); }
                if (xB < Pn) { p0[xB] = fmaxf(acc[g][2] + b0, 0.f);
                               p1[xB] = fmaxf(acc[g][3] + b1, 0.f); }
            }
        }
    }
}

// ============================================================
// K6: conv2 (32 -> 8 ch, 3x3 SAME, relu) via tf32 mma.m16n8k8.
// ic processed in 4 chunks of 8 (smem refill); acc persists per warp-tile.
// ============================================================
__global__ __launch_bounds__(256) void conv2_kernel(const float* __restrict__ w,
                                                    const float* __restrict__ bias)
{
    const int n  = blockIdx.z;
    const int x0 = blockIdx.x * 64;
    const int y0 = blockIdx.y * 16;
    __shared__ unsigned sIn[18*68*9];
    __shared__ float sB[8];
    const int tid  = threadIdx.x;
    const int lane = tid & 31, wid = tid >> 5;
    const int qr = lane >> 2, icb = lane & 3;

    // B fragments: [shift][kchunk][2], oc = qr (N=8)
    unsigned bf[9][4][2];
    #pragma unroll
    for (int s = 0; s < 9; s++)
        #pragma unroll
        for (int kc = 0; kc < 4; kc++) {
            bf[s][kc][0] = tf32_of(w[(qr*32 + kc*8 + icb)*9 + s]);
            bf[s][kc][1] = tf32_of(w[(qr*32 + kc*8 + icb + 4)*9 + s]);
        }
    if (tid < 8) sB[tid] = bias[tid];

    float acc[8][4] = {};

    #pragma unroll 1
    for (int kc = 0; kc < 4; kc++) {
        __syncthreads();
        for (int i = tid; i < 18*68; i += 256) {
            int r = i / 68, c = i - r*68;
            int gy = y0 - 1 + r, gx = x0 - 1 + c;
            bool ok = (c < 66) && gy >= 0 && gy < Pn && gx >= 0 && gx < Pn;
            const float* base = g_C1 + (size_t)(n*C1C + kc*8)*PP2 + (size_t)gy*Pn + gx;
            #pragma unroll
            for (int ic = 0; ic < 8; ic++) {
                float v = ok ? base[(size_t)ic*PP2] : 0.f;
                sIn[i*9 + ic] = tf32_of(v);
            }
        }
        __syncthreads();

        #pragma unroll 1
        for (int j = 0; j < 8; j++) {
            int t = wid*8 + j;
            int ty = t >> 2;
            int xs = (t & 3) * 16;
            #pragma unroll
            for (int ky = 0; ky < 3; ky++) {
                #pragma unroll
                for (int kx = 0; kx < 3; kx++) {
                    int rb = (ty + ky)*68 + xs + kx;
                    unsigned a[4];
                    a[0] = sIn[(rb + qr)*9 + icb];
                    a[1] = sIn[(rb + qr + 8)*9 + icb];
                    a[2] = sIn[(rb + qr)*9 + icb + 4];
                    a[3] = sIn[(rb + qr + 8)*9 + icb + 4];
                    mma_tf32(acc[j], a, bf[ky*3 + kx][kc]);
                }
            }
        }
    }

    #pragma unroll 1
    for (int j = 0; j < 8; j++) {
        int t = wid*8 + j;
        int ty = t >> 2;
        int xs = (t & 3) * 16;
        int y = y0 + ty;
        if (y >= Pn) continue;
        int xA = x0 + xs + qr, xB = xA + 8;
        int oc = 2*icb;
        float b0 = sB[oc], b1 = sB[oc+1];
        float* p0 = g_S + (size_t)(n*Hn + oc)*PP2 + (size_t)y*Pn;
        float* p1 = p0 + PP2;
        if (xA < Pn) { p0[xA] = fmaxf(acc[j][0] + b0, 0.f);
                       p1[xA] = fmaxf(acc[j][1] + b1, 0.f); }
        if (xB < Pn) { p0[xB] = fmaxf(acc[j][2] + b0, 0.f);
                       p1[xB] = fmaxf(acc[j][3] + b1, 0.f); }
    }
}

// ============================================================
// K7: out[b,p] = mean_h sum_q attn2[b,h,p,q] * value[b,q]
// ============================================================
__global__ __launch_bounds__(256) void final_kernel(const float* __restrict__ value,
                                                    float* __restrict__ out)
{
    const int bp = blockIdx.x;
    const int b = bp / Pn, p = bp % Pn;
    const float* vrow = value + b*Pn;
    const int tid = threadIdx.x;
    float s = 0.f;
    #pragma unroll
    for (int h = 0; h < Hn; h++) {
        const float* ar = g_S + (size_t)(b*Hn + h)*PP2 + p*Pn;
        for (int q = tid; q < Pn; q += 256) s += ar[q] * vrow[q];
    }
    __shared__ float red[256];
    red[tid] = s; __syncthreads();
    for (int st = 128; st > 0; st >>= 1) { if (tid < st) red[tid] += red[tid+st]; __syncthreads(); }
    if (tid == 0) out[bp] = red[0] * 0.125f;
}

// ============================================================
extern "C" void kernel_launch(void* const* d_in, const int* in_sizes, int n_in,
                              void* d_out, int out_size)
{
    const float* query = (const float*)d_in[0];
    const float* key_t = (const float*)d_in[1];
    const float* value = (const float*)d_in[2];
    const float* Wq    = (const float*)d_in[3];
    const float* bq    = (const float*)d_in[4];
    const float* Wk    = (const float*)d_in[5];
    const float* bk    = (const float*)d_in[6];
    const float* c1w   = (const float*)d_in[7];
    const float* c1b   = (const float*)d_in[8];
    const float* c2w   = (const float*)d_in[9];
    const float* c2b   = (const float*)d_in[10];
    float* out = (float*)d_out;

    proj_kernel<<<dim3(8, 57), 256>>>(query, Wq, bq, 0);
    proj_kernel<<<dim3(8, 57), 256>>>(key_t, Wk, bk, 1);
    scores_kernel<<<dim3(15, 15, 32), 256>>>();
    argmax_kernel<<<dim3(15, 32), 256>>>();
    modsm_kernel<<<dim3(BHn*Pn), 256>>>();
    conv1_kernel<<<dim3(15, 57, 4), 256>>>(c1w, c1b);
    conv2_kernel<<<dim3(15, 57, 4), 256>>>(c2w, c2b);
    final_kernel<<<dim3(Bn*Pn), 256>>>(value, out);
}

// round 8
// speedup vs baseline: 2.0058x; 1.2513x over previous
#include <cuda_runtime.h>
#include <cuda_bf16.h>

#define Bn   4
#define Pn   900
#define Hn   8
#define DKn  64
#define DMn  512
#define PP2  (Pn*Pn)      // 810000
#define BHn  (Bn*Hn)      // 32
#define C1C  32

typedef unsigned long long u64_t;

// ---- packed dual-fp32 FMA helpers (Blackwell f32x2 pipe) ----
__device__ __forceinline__ u64_t fma2(u64_t a, u64_t b, u64_t c) {
    u64_t d;
    asm("fma.rn.f32x2 %0, %1, %2, %3;" : "=l"(d) : "l"(a), "l"(b), "l"(c));
    return d;
}
__device__ __forceinline__ u64_t dup2f(float v) {
    u64_t d;
    asm("mov.b64 %0, {%1, %1};" : "=l"(d) : "r"(__float_as_uint(v)));
    return d;
}
__device__ __forceinline__ float2 unp2(u64_t v) {
    unsigned lo, hi;
    asm("mov.b64 {%0, %1}, %2;" : "=r"(lo), "=r"(hi) : "l"(v));
    float2 r; r.x = __uint_as_float(lo); r.y = __uint_as_float(hi);
    return r;
}

// ---- tf32 tensor-core helpers ----
__device__ __forceinline__ unsigned tf32_of(float f) {
    unsigned u;
    asm("cvt.rna.tf32.f32 %0, %1;" : "=r"(u) : "f"(f));
    return u;
}
__device__ __forceinline__ void mma_tf32(float* c, const unsigned* a, const unsigned* b) {
    asm("mma.sync.aligned.m16n8k8.row.col.f32.tf32.tf32.f32 "
        "{%0,%1,%2,%3}, {%4,%5,%6,%7}, {%8,%9}, {%0,%1,%2,%3};"
        : "+f"(c[0]), "+f"(c[1]), "+f"(c[2]), "+f"(c[3])
        : "r"(a[0]), "r"(a[1]), "r"(a[2]), "r"(a[3]), "r"(b[0]), "r"(b[1]));
}

// ---- scratch (static device allocations; no runtime alloc) ----
__device__ float g_QP[Bn*Hn*Pn*DKn];        // [b,h,p,c]
__device__ float g_KP[Bn*Hn*Pn*DKn];        // [b,h,p,c]
__device__ float g_S [BHn*PP2];             // scores -> attn (conv input)
__device__ float g_C1[Bn*Hn*PP2];           // conv2 output (fused kernel)
__device__ int   g_IDX[BHn*Pn];             // argmax per (bh, key q)

// ============================================================
// K1: projection GEMM (fp32 f32x2 — feeds argmax-sensitive path)
// ============================================================
__global__ __launch_bounds__(256) void proj_kernel(const float* __restrict__ A,
                                                   const float* __restrict__ W,
                                                   const float* __restrict__ bias,
                                                   int which)
{
    float* out = which ? g_KP : g_QP;
    __shared__ __align__(16) float As[16][68];
    __shared__ __align__(16) float Bs[16][68];
    const int bm = blockIdx.y * 64;
    const int bn = blockIdx.x * 64;
    const int tid = threadIdx.x;
    const int lk = tid & 15, lm = tid >> 4;
    const int tx = tid & 15, ty = tid >> 4;
    u64_t acc2[4][2] = {};
    for (int k0 = 0; k0 < DMn; k0 += 16) {
        #pragma unroll
        for (int i = 0; i < 4; i++) {
            int m = bm + lm + i*16;
            As[lk][lm + i*16] = (m < Bn*Pn) ? A[m*DMn + k0 + lk] : 0.f;
            Bs[lk][lm + i*16] = W[(bn + lm + i*16)*DMn + k0 + lk];
        }
        __syncthreads();
        #pragma unroll
        for (int k = 0; k < 16; k++) {
            float4 av = *(const float4*)&As[k][ty*4];
            const u64_t* bp = (const u64_t*)&Bs[k][tx*4];
            u64_t b01 = bp[0], b23 = bp[1];
            u64_t a_[4] = {dup2f(av.x), dup2f(av.y), dup2f(av.z), dup2f(av.w)};
            #pragma unroll
            for (int i = 0; i < 4; i++) {
                acc2[i][0] = fma2(a_[i], b01, acc2[i][0]);
                acc2[i][1] = fma2(a_[i], b23, acc2[i][1]);
            }
        }
        __syncthreads();
    }
    #pragma unroll
    for (int i = 0; i < 4; i++) {
        int m = bm + ty*4 + i;
        if (m >= Bn*Pn) continue;
        int b = m / Pn, p = m % Pn;
        #pragma unroll
        for (int jp = 0; jp < 2; jp++) {
            float2 v = unp2(acc2[i][jp]);
            int n0 = bn + tx*4 + jp*2;
            out[((b*Hn + (n0 >> 6))*Pn + p)*DKn + (n0 & 63)]       = v.x + bias[n0];
            out[((b*Hn + ((n0+1) >> 6))*Pn + p)*DKn + ((n0+1) & 63)] = v.y + bias[n0+1];
        }
    }
}

// ============================================================
// K2: scores (fp32 f32x2)
// ============================================================
__global__ __launch_bounds__(256) void scores_kernel()
{
    const int bh = blockIdx.z;
    const float* Q = g_QP + bh*Pn*DKn;
    const float* K = g_KP + bh*Pn*DKn;
    __shared__ __align__(16) float Qs[64][68];   // [k][row]
    __shared__ __align__(16) float Ks[64][68];   // [k][row]
    const int p0 = blockIdx.y*64, q0 = blockIdx.x*64;
    const int tid = threadIdx.x;
    #pragma unroll
    for (int i = 0; i < 16; i++) {
        int idx = tid + i*256;
        int r = idx >> 6, c = idx & 63;
        Qs[c][r] = (p0 + r < Pn) ? Q[(p0+r)*DKn + c] : 0.f;
        Ks[c][r] = (q0 + r < Pn) ? K[(q0+r)*DKn + c] : 0.f;
    }
    __syncthreads();
    const int tx = tid & 15, ty = tid >> 4;
    u64_t acc2[4][2] = {};
    #pragma unroll 8
    for (int k = 0; k < 64; k++) {
        float4 av = *(const float4*)&Qs[k][ty*4];
        const u64_t* bp = (const u64_t*)&Ks[k][tx*4];
        u64_t b01 = bp[0], b23 = bp[1];
        u64_t a_[4] = {dup2f(av.x), dup2f(av.y), dup2f(av.z), dup2f(av.w)};
        #pragma unroll
        for (int i = 0; i < 4; i++) {
            acc2[i][0] = fma2(a_[i], b01, acc2[i][0]);
            acc2[i][1] = fma2(a_[i], b23, acc2[i][1]);
        }
    }
    float* Sb = g_S + bh*PP2;
    #pragma unroll
    for (int i = 0; i < 4; i++) {
        int p = p0 + ty*4 + i;
        if (p >= Pn) continue;
        #pragma unroll
        for (int jp = 0; jp < 2; jp++) {
            float2 v = unp2(acc2[i][jp]);
            int q = q0 + tx*4 + jp*2;
            if (q < Pn)     Sb[p*Pn + q]     = v.x;
            if (q + 1 < Pn) Sb[p*Pn + q + 1] = v.y;
        }
    }
}

// ============================================================
// K3: argmax over p per (bh, q), first-occurrence ties.
// ============================================================
__global__ __launch_bounds__(256) void argmax_kernel()
{
    const int bh = blockIdx.y;
    const int tid = threadIdx.x;
    const int qi = (tid & 63) + blockIdx.x*64;
    const int rg = tid >> 6;
    const float* Sb = g_S + bh*PP2;
    float best = -1e30f; int bi = 0;
    if (qi < Pn) {
        int r0 = rg*225;
        #pragma unroll 5
        for (int p = r0; p < r0 + 225; p++) {
            float v = Sb[p*Pn + qi];
            if (v > best) { best = v; bi = p; }
        }
    }
    __shared__ float sv[256];
    __shared__ int   si[256];
    sv[tid] = best; si[tid] = bi;
    __syncthreads();
    if (rg == 0 && qi < Pn) {
        #pragma unroll
        for (int g = 1; g < 4; g++) {
            float v = sv[tid + g*64];
            int   ii = si[tid + g*64];
            if (v > best) { best = v; bi = ii; }
        }
        g_IDX[bh*Pn + qi] = bi;
    }
}

// ============================================================
// K4: gaussian modulation + scale + softmax
// ============================================================
__global__ __launch_bounds__(256) void modsm_kernel()
{
    const int row = blockIdx.x;
    const int bh = row / Pn, p = row % Pn;
    float* Srow = g_S + bh*PP2 + p*Pn;
    const int* idxr = g_IDX + bh*Pn;
    const int ys = p / 30, xs = p % 30;
    const float ysc = -1.f + (2.f/29.f)*(float)ys;
    const float xsc = -1.f + (2.f/29.f)*(float)xs;
    const int tid = threadIdx.x;

    __shared__ float buf[Pn];
    __shared__ float red[256];

    float lmax = -1e30f;
    for (int q = tid; q < Pn; q += 256) {
        int id = idxr[q];
        float fy = (float)(id / 30);
        float fx = (float)(id - (id/30)*30);
        float dx = xsc - fx, dy = ysc - fy;
        float g = __expf(-(dx*dx + dy*dy) * 0.02f);
        float v = g * Srow[q] * 0.125f;
        buf[q] = v;
        lmax = fmaxf(lmax, v);
    }
    red[tid] = lmax; __syncthreads();
    for (int s = 128; s > 0; s >>= 1) { if (tid < s) red[tid] = fmaxf(red[tid], red[tid+s]); __syncthreads(); }
    const float m = red[0];
    __syncthreads();

    float lsum = 0.f;
    for (int q = tid; q < Pn; q += 256) {
        float e = __expf(buf[q] - m);
        buf[q] = e;
        lsum += e;
    }
    red[tid] = lsum; __syncthreads();
    for (int s = 128; s > 0; s >>= 1) { if (tid < s) red[tid] += red[tid+s]; __syncthreads(); }
    const float inv = 1.f / red[0];
    for (int q = tid; q < Pn; q += 256) Srow[q] = buf[q] * inv;
}

// ============================================================
// K5: FUSED conv1+conv2 (8->32->8 ch, both 3x3 SAME + relu), tf32 MMA.
// Block = 16x32 conv2-output tile. Mid tile (18x34x32, tf32) lives in smem.
// sIn  layout [ic][pos], pos-pad 728  (conflict-free A loads phase 1)
// sMid layout [oc][pos], pos-pad 616  (conflict-free A loads phase 2)
// ============================================================
#define FT_Y   16
#define FT_X   32
#define MID_W  34
#define MID_N  612          // 18*34
#define IN_W   36
#define IN_N   720          // 20*36
#define PIN    728
#define PMID   616
#define SMEM_FUSED ((8*PIN + 32*PMID)*4)   // 102144 bytes

__global__ __launch_bounds__(256) void fused_conv_kernel(const float* __restrict__ w1,
                                                         const float* __restrict__ b1,
                                                         const float* __restrict__ w2,
                                                         const float* __restrict__ b2)
{
    extern __shared__ unsigned dsm[];
    unsigned* sIn  = dsm;               // 8  x 728
    unsigned* sMid = dsm + 8*PIN;       // 32 x 616
    __shared__ float sB1[32];
    __shared__ float sB2[8];

    const int n  = blockIdx.z;
    const int X0 = blockIdx.x * FT_X;
    const int Y0 = blockIdx.y * FT_Y;
    const int tid  = threadIdx.x;
    const int lane = tid & 31, wid = tid >> 5;
    const int qr = lane >> 2, icb = lane & 3;

    if (tid < 32) sB1[tid] = b1[tid];
    if (tid < 8)  sB2[tid] = b2[tid];

    // ---- stage input 20x36 x 8ch (tf32) ----
    for (int i = tid; i < IN_N; i += 256) {
        int r = i / IN_W, c = i - r*IN_W;
        int gy = Y0 - 2 + r, gx = X0 - 2 + c;
        bool ok = (gy >= 0 && gy < Pn && gx >= 0 && gx < Pn);
        const float* base = g_S + (size_t)(n*8)*PP2 + (size_t)gy*Pn + gx;
        #pragma unroll
        for (int ic = 0; ic < 8; ic++) {
            float v = ok ? base[(size_t)ic*PP2] : 0.f;
            sIn[ic*PIN + i] = tf32_of(v);
        }
    }

    // ---- conv1 weight fragments: [shift][ocg][2], oc = g*8+qr, k = icb ----
    unsigned bf[9][4][2];
    #pragma unroll
    for (int s = 0; s < 9; s++)
        #pragma unroll
        for (int g = 0; g < 4; g++) {
            int oc = g*8 + qr;
            bf[s][g][0] = tf32_of(w1[(oc*8 + icb)*9 + s]);
            bf[s][g][1] = tf32_of(w1[(oc*8 + icb + 4)*9 + s]);
        }
    __syncthreads();

    // ---- phase 1: conv1 -> sMid (18x34 mid pixels, 39 M16 tiles) ----
    for (int t = wid; t < 39; t += 8) {
        int pr0 = t*16 + qr;
        int pr1 = pr0 + 8;
        int q0 = pr0 < MID_N ? pr0 : MID_N - 1;
        int q1 = pr1 < MID_N ? pr1 : MID_N - 1;
        int my0 = q0 / MID_W, mx0 = q0 - my0*MID_W;
        int my1 = q1 / MID_W, mx1 = q1 - my1*MID_W;
        int base0 = my0*IN_W + mx0;
        int base1 = my1*IN_W + mx1;
        float acc[4][4] = {};
        #pragma unroll
        for (int ky = 0; ky < 3; ky++) {
            #pragma unroll
            for (int kx = 0; kx < 3; kx++) {
                int off = ky*IN_W + kx;
                unsigned a[4];
                a[0] = sIn[icb*PIN     + base0 + off];
                a[1] = sIn[icb*PIN     + base1 + off];
                a[2] = sIn[(icb+4)*PIN + base0 + off];
                a[3] = sIn[(icb+4)*PIN + base1 + off];
                int s = ky*3 + kx;
                #pragma unroll
                for (int g = 0; g < 4; g++) mma_tf32(acc[g], a, bf[s][g]);
            }
        }
        // store (relu+bias); mid pixels outside image => exact 0 (SAME padding)
        bool s0 = pr0 < MID_N, s1 = pr1 < MID_N;
        int gy0 = Y0 - 1 + my0, gx0 = X0 - 1 + mx0;
        int gy1 = Y0 - 1 + my1, gx1 = X0 - 1 + mx1;
        bool in0 = (gy0 >= 0 && gy0 < Pn && gx0 >= 0 && gx0 < Pn);
        bool in1 = (gy1 >= 0 && gy1 < Pn && gx1 >= 0 && gx1 < Pn);
        #pragma unroll
        for (int g = 0; g < 4; g++) {
            int oc = g*8 + 2*icb;
            if (s0) {
                float v0 = in0 ? fmaxf(acc[g][0] + sB1[oc],   0.f) : 0.f;
                float v1 = in0 ? fmaxf(acc[g][1] + sB1[oc+1], 0.f) : 0.f;
                sMid[oc*PMID + q0]     = tf32_of(v0);
                sMid[(oc+1)*PMID + q0] = tf32_of(v1);
            }
            if (s1) {
                float v2 = in1 ? fmaxf(acc[g][2] + sB1[oc],   0.f) : 0.f;
                float v3 = in1 ? fmaxf(acc[g][3] + sB1[oc+1], 0.f) : 0.f;
                sMid[oc*PMID + q1]     = tf32_of(v2);
                sMid[(oc+1)*PMID + q1] = tf32_of(v3);
            }
        }
    }
    __syncthreads();

    // ---- conv2 weight fragments (overwrite bf): [shift][kchunk][2], oc=qr ----
    #pragma unroll
    for (int s = 0; s < 9; s++)
        #pragma unroll
        for (int kc = 0; kc < 4; kc++) {
            bf[s][kc][0] = tf32_of(w2[(qr*32 + kc*8 + icb)*9 + s]);
            bf[s][kc][1] = tf32_of(w2[(qr*32 + kc*8 + icb + 4)*9 + s]);
        }

    // ---- phase 2: conv2 from sMid -> g_C1 (16x32 out pixels, 32 M16 tiles) ----
    for (int t = wid; t < 32; t += 8) {
        int p0 = t*16 + qr;
        int p1 = p0 + 8;
        int oy0 = p0 >> 5, ox0 = p0 & 31;
        int oy1 = p1 >> 5, ox1 = p1 & 31;
        float acc[4] = {};
        #pragma unroll
        for (int ky = 0; ky < 3; ky++) {
            #pragma unroll
            for (int kx = 0; kx < 3; kx++) {
                int r0 = (oy0 + ky)*MID_W + ox0 + kx;
                int r1 = (oy1 + ky)*MID_W + ox1 + kx;
                int s = ky*3 + kx;
                #pragma unroll
                for (int kc = 0; kc < 4; kc++) {
                    unsigned a[4];
                    a[0] = sMid[(kc*8 + icb)*PMID     + r0];
                    a[1] = sMid[(kc*8 + icb)*PMID     + r1];
                    a[2] = sMid[(kc*8 + icb + 4)*PMID + r0];
                    a[3] = sMid[(kc*8 + icb + 4)*PMID + r1];
                    mma_tf32(acc, a, bf[s][kc]);
                }
            }
        }
        int oc = 2*icb;
        float bb0 = sB2[oc], bb1 = sB2[oc+1];
        int y0g = Y0 + oy0, x0g = X0 + ox0;
        int y1g = Y0 + oy1, x1g = X0 + ox1;
        if (y0g < Pn && x0g < Pn) {
            float* d = g_C1 + (size_t)(n*Hn + oc)*PP2 + (size_t)y0g*Pn + x0g;
            d[0]   = fmaxf(acc[0] + bb0, 0.f);
            d[PP2] = fmaxf(acc[1] + bb1, 0.f);
        }
        if (y1g < Pn && x1g < Pn) {
            float* d = g_C1 + (size_t)(n*Hn + oc)*PP2 + (size_t)y1g*Pn + x1g;
            d[0]   = fmaxf(acc[2] + bb0, 0.f);
            d[PP2] = fmaxf(acc[3] + bb1, 0.f);
        }
    }
}

// ============================================================
// K7: out[b,p] = mean_h sum_q attn2[b,h,p,q] * value[b,q]
// ============================================================
__global__ __launch_bounds__(256) void final_kernel(const float* __restrict__ value,
                                                    float* __restrict__ out)
{
    const int bp = blockIdx.x;
    const int b = bp / Pn, p = bp % Pn;
    const float* vrow = value + b*Pn;
    const int tid = threadIdx.x;
    float s = 0.f;
    #pragma unroll
    for (int h = 0; h < Hn; h++) {
        const float* ar = g_C1 + (size_t)(b*Hn + h)*PP2 + p*Pn;
        for (int q = tid; q < Pn; q += 256) s += ar[q] * vrow[q];
    }
    __shared__ float red[256];
    red[tid] = s; __syncthreads();
    for (int st = 128; st > 0; st >>= 1) { if (tid < st) red[tid] += red[tid+st]; __syncthreads(); }
    if (tid == 0) out[bp] = red[0] * 0.125f;
}

// ============================================================
extern "C" void kernel_launch(void* const* d_in, const int* in_sizes, int n_in,
                              void* d_out, int out_size)
{
    const float* query = (const float*)d_in[0];
    const float* key_t = (const float*)d_in[1];
    const float* value = (const float*)d_in[2];
    const float* Wq    = (const float*)d_in[3];
    const float* bq    = (const float*)d_in[4];
    const float* Wk    = (const float*)d_in[5];
    const float* bk    = (const float*)d_in[6];
    const float* c1w   = (const float*)d_in[7];
    const float* c1b   = (const float*)d_in[8];
    const float* c2w   = (const float*)d_in[9];
    const float* c2b   = (const float*)d_in[10];
    float* out = (float*)d_out;

    static int smem_set = 0;
    if (!smem_set) {
        cudaFuncSetAttribute(fused_conv_kernel,
                             cudaFuncAttributeMaxDynamicSharedMemorySize, SMEM_FUSED);
        smem_set = 1;
    }

    proj_kernel<<<dim3(8, 57), 256>>>(query, Wq, bq, 0);
    proj_kernel<<<dim3(8, 57), 256>>>(key_t, Wk, bk, 1);
    scores_kernel<<<dim3(15, 15, 32), 256>>>();
    argmax_kernel<<<dim3(15, 32), 256>>>();
    modsm_kernel<<<dim3(BHn*Pn), 256>>>();
    fused_conv_kernel<<<dim3(29, 57, 4), 256, SMEM_FUSED>>>(c1w, c1b, c2w, c2b);
    final_kernel<<<dim3(Bn*Pn), 256>>>(value, out);
}

// round 9
// speedup vs baseline: 2.0924x; 1.0431x over previous
#include <cuda_runtime.h>
#include <cuda_bf16.h>

#define Bn   4
#define Pn   900
#define Hn   8
#define DKn  64
#define DMn  512
#define PP2  (Pn*Pn)      // 810000
#define BHn  (Bn*Hn)      // 32
#define C1C  32

typedef unsigned long long u64_t;

// ---- packed dual-fp32 FMA helpers (Blackwell f32x2 pipe) ----
__device__ __forceinline__ u64_t fma2(u64_t a, u64_t b, u64_t c) {
    u64_t d;
    asm("fma.rn.f32x2 %0, %1, %2, %3;" : "=l"(d) : "l"(a), "l"(b), "l"(c));
    return d;
}
__device__ __forceinline__ u64_t dup2f(float v) {
    u64_t d;
    asm("mov.b64 %0, {%1, %1};" : "=l"(d) : "r"(__float_as_uint(v)));
    return d;
}
__device__ __forceinline__ float2 unp2(u64_t v) {
    unsigned lo, hi;
    asm("mov.b64 {%0, %1}, %2;" : "=r"(lo), "=r"(hi) : "l"(v));
    float2 r; r.x = __uint_as_float(lo); r.y = __uint_as_float(hi);
    return r;
}

// ---- tf32 tensor-core helpers ----
__device__ __forceinline__ unsigned tf32_of(float f) {
    unsigned u;
    asm("cvt.rna.tf32.f32 %0, %1;" : "=r"(u) : "f"(f));
    return u;
}
__device__ __forceinline__ void mma_tf32(float* c, const unsigned* a, const unsigned* b) {
    asm("mma.sync.aligned.m16n8k8.row.col.f32.tf32.tf32.f32 "
        "{%0,%1,%2,%3}, {%4,%5,%6,%7}, {%8,%9}, {%0,%1,%2,%3};"
        : "+f"(c[0]), "+f"(c[1]), "+f"(c[2]), "+f"(c[3])
        : "r"(a[0]), "r"(a[1]), "r"(a[2]), "r"(a[3]), "r"(b[0]), "r"(b[1]));
}

// order-preserving float->uint (monotonic for all finite values)
__device__ __forceinline__ unsigned ord_f(float v) {
    unsigned b = __float_as_uint(v);
    return (b & 0x80000000u) ? ~b : (b | 0x80000000u);
}
__device__ __forceinline__ u64_t amax_key(float v, int p) {
    return ((u64_t)ord_f(v) << 32) | (u64_t)(0xFFFFFFFFu - (unsigned)p);
}

// ---- scratch (static device allocations; no runtime alloc) ----
__device__ float g_QP[Bn*Hn*Pn*DKn];        // [b,h,p,c]
__device__ float g_KP[Bn*Hn*Pn*DKn];        // [b,h,p,c]
__device__ float g_S [BHn*PP2];             // scores -> attn (conv input)
__device__ float g_C1[Bn*Hn*PP2];           // conv2 output (fused kernel)
__device__ u64_t g_AMX[BHn*Pn];             // packed (value, ~p) argmax keys

// ============================================================
// K1: projection GEMM (fp32 f32x2 — feeds argmax-sensitive path)
// ============================================================
__global__ __launch_bounds__(256) void proj_kernel(const float* __restrict__ A,
                                                   const float* __restrict__ W,
                                                   const float* __restrict__ bias,
                                                   int which)
{
    float* out = which ? g_KP : g_QP;
    __shared__ __align__(16) float As[16][68];
    __shared__ __align__(16) float Bs[16][68];
    const int bm = blockIdx.y * 64;
    const int bn = blockIdx.x * 64;
    const int tid = threadIdx.x;
    const int lk = tid & 15, lm = tid >> 4;
    const int tx = tid & 15, ty = tid >> 4;
    u64_t acc2[4][2] = {};
    for (int k0 = 0; k0 < DMn; k0 += 16) {
        #pragma unroll
        for (int i = 0; i < 4; i++) {
            int m = bm + lm + i*16;
            As[lk][lm + i*16] = (m < Bn*Pn) ? A[m*DMn + k0 + lk] : 0.f;
            Bs[lk][lm + i*16] = W[(bn + lm + i*16)*DMn + k0 + lk];
        }
        __syncthreads();
        #pragma unroll
        for (int k = 0; k < 16; k++) {
            float4 av = *(const float4*)&As[k][ty*4];
            const u64_t* bp = (const u64_t*)&Bs[k][tx*4];
            u64_t b01 = bp[0], b23 = bp[1];
            u64_t a_[4] = {dup2f(av.x), dup2f(av.y), dup2f(av.z), dup2f(av.w)};
            #pragma unroll
            for (int i = 0; i < 4; i++) {
                acc2[i][0] = fma2(a_[i], b01, acc2[i][0]);
                acc2[i][1] = fma2(a_[i], b23, acc2[i][1]);
            }
        }
        __syncthreads();
    }
    #pragma unroll
    for (int i = 0; i < 4; i++) {
        int m = bm + ty*4 + i;
        if (m >= Bn*Pn) continue;
        int b = m / Pn, p = m % Pn;
        #pragma unroll
        for (int jp = 0; jp < 2; jp++) {
            float2 v = unp2(acc2[i][jp]);
            int n0 = bn + tx*4 + jp*2;
            out[((b*Hn + (n0 >> 6))*Pn + p)*DKn + (n0 & 63)]       = v.x + bias[n0];
            out[((b*Hn + ((n0+1) >> 6))*Pn + p)*DKn + ((n0+1) & 63)] = v.y + bias[n0+1];
        }
    }
}

// ============================================================
// K2: scores via tf32 3-MMA split precision + fused argmax.
// S[bh,p,q] = sum_c QP[bh,p,c]*KP[bh,q,c]; acc += hh + hl + lh.
// Block 64p x 64q; warp = m16 x n32; argmax keys -> atomicMax(g_AMX).
// ============================================================
#define SC_SMEM (4*64*68*4)     // Qhi,Qlo,Khi,Klo u32 tiles = 69632 B

__global__ __launch_bounds__(256) void scores_kernel()
{
    extern __shared__ unsigned sc[];
    unsigned* Qhi = sc;
    unsigned* Qlo = sc + 64*68;
    unsigned* Khi = sc + 2*64*68;
    unsigned* Klo = sc + 3*64*68;

    const int bh = blockIdx.z;
    const float* Q = g_QP + bh*Pn*DKn;
    const float* K = g_KP + bh*Pn*DKn;
    const int p0 = blockIdx.y*64, q0 = blockIdx.x*64;
    const int tid = threadIdx.x;
    const int lane = tid & 31, wid = tid >> 5;
    const int qr = lane >> 2, icb = lane & 3;

    // stage + split (hi = tf32 round, lo = tf32(v - hi))
    #pragma unroll
    for (int i = 0; i < 16; i++) {
        int idx = tid + i*256;
        int r = idx >> 6, c = idx & 63;
        float qv = (p0 + r < Pn) ? Q[(p0+r)*DKn + c] : 0.f;
        float kv = (q0 + r < Pn) ? K[(q0+r)*DKn + c] : 0.f;
        unsigned qh = tf32_of(qv);
        unsigned kh = tf32_of(kv);
        Qhi[r*68 + c] = qh;
        Qlo[r*68 + c] = tf32_of(qv - __uint_as_float(qh));
        Khi[r*68 + c] = kh;
        Klo[r*68 + c] = tf32_of(kv - __uint_as_float(kh));
    }
    __syncthreads();

    const int m0 = (wid & 3) * 16;     // p sub-tile
    const int n0 = (wid >> 2) * 32;    // q sub-tile (4 n8 tiles)
    float acc[4][4] = {};

    #pragma unroll
    for (int ks = 0; ks < 8; ks++) {
        int k0 = ks*8;
        unsigned ah[4], al[4];
        int rA = (m0 + qr)*68 + k0 + icb;
        int rB = (m0 + qr + 8)*68 + k0 + icb;
        ah[0] = Qhi[rA];     ah[1] = Qhi[rB];
        ah[2] = Qhi[rA + 4]; ah[3] = Qhi[rB + 4];
        al[0] = Qlo[rA];     al[1] = Qlo[rB];
        al[2] = Qlo[rA + 4]; al[3] = Qlo[rB + 4];
        #pragma unroll
        for (int j = 0; j < 4; j++) {
            int rK = (n0 + j*8 + qr)*68 + k0 + icb;
            unsigned bh_[2] = { Khi[rK], Khi[rK + 4] };
            unsigned bl_[2] = { Klo[rK], Klo[rK + 4] };
            mma_tf32(acc[j], ah, bh_);
            mma_tf32(acc[j], ah, bl_);
            mma_tf32(acc[j], al, bh_);
        }
    }

    // epilogue: write scores + fused argmax over p columns
    float* Sb = g_S + bh*PP2;
    const int pA = p0 + m0 + qr, pB = pA + 8;
    const bool vA = pA < Pn, vB = pB < Pn;
    #pragma unroll
    for (int j = 0; j < 4; j++) {
        int qa = q0 + n0 + j*8 + 2*icb;
        int qb = qa + 1;
        if (vA) {
            if (qa < Pn) Sb[pA*Pn + qa] = acc[j][0];
            if (qb < Pn) Sb[pA*Pn + qb] = acc[j][1];
        }
        if (vB) {
            if (qa < Pn) Sb[pB*Pn + qa] = acc[j][2];
            if (qb < Pn) Sb[pB*Pn + qb] = acc[j][3];
        }
        // key = (ordered value, ~p): max => (value desc, p asc) = first-occurrence argmax
        u64_t ka = 0, kb = 0;
        if (vA) { ka = amax_key(acc[j][0], pA); kb = amax_key(acc[j][1], pA); }
        if (vB) {
            u64_t t = amax_key(acc[j][2], pB); if (t > ka) ka = t;
            t = amax_key(acc[j][3], pB);       if (t > kb) kb = t;
        }
        #pragma unroll
        for (int m = 4; m <= 16; m <<= 1) {
            u64_t ta = __shfl_xor_sync(0xFFFFFFFFu, ka, m);
            u64_t tb = __shfl_xor_sync(0xFFFFFFFFu, kb, m);
            if (ta > ka) ka = ta;
            if (tb > kb) kb = tb;
        }
        if (qr == 0) {
            if (qa < Pn) atomicMax(&g_AMX[bh*Pn + qa], ka);
            if (qb < Pn) atomicMax(&g_AMX[bh*Pn + qb], kb);
        }
    }
}

// ============================================================
// K4: gaussian modulation + scale + softmax
// ============================================================
__global__ __launch_bounds__(256) void modsm_kernel()
{
    const int row = blockIdx.x;
    const int bh = row / Pn, p = row % Pn;
    float* Srow = g_S + bh*PP2 + p*Pn;
    const u64_t* keyr = g_AMX + bh*Pn;
    const int ys = p / 30, xs = p % 30;
    const float ysc = -1.f + (2.f/29.f)*(float)ys;
    const float xsc = -1.f + (2.f/29.f)*(float)xs;
    const int tid = threadIdx.x;

    __shared__ float buf[Pn];
    __shared__ float red[256];

    float lmax = -1e30f;
    for (int q = tid; q < Pn; q += 256) {
        int id = (int)(0xFFFFFFFFu - (unsigned)(keyr[q] & 0xFFFFFFFFu));
        float fy = (float)(id / 30);
        float fx = (float)(id - (id/30)*30);
        float dx = xsc - fx, dy = ysc - fy;
        float g = __expf(-(dx*dx + dy*dy) * 0.02f);
        float v = g * Srow[q] * 0.125f;
        buf[q] = v;
        lmax = fmaxf(lmax, v);
    }
    red[tid] = lmax; __syncthreads();
    for (int s = 128; s > 0; s >>= 1) { if (tid < s) red[tid] = fmaxf(red[tid], red[tid+s]); __syncthreads(); }
    const float m = red[0];
    __syncthreads();

    float lsum = 0.f;
    for (int q = tid; q < Pn; q += 256) {
        float e = __expf(buf[q] - m);
        buf[q] = e;
        lsum += e;
    }
    red[tid] = lsum; __syncthreads();
    for (int s = 128; s > 0; s >>= 1) { if (tid < s) red[tid] += red[tid+s]; __syncthreads(); }
    const float inv = 1.f / red[0];
    for (int q = tid; q < Pn; q += 256) Srow[q] = buf[q] * inv;
}

// ============================================================
// K5: FUSED conv1+conv2 (8->32->8 ch, both 3x3 SAME + relu), tf32 MMA.
// ============================================================
#define FT_Y   16
#define FT_X   32
#define MID_W  34
#define MID_N  612          // 18*34
#define IN_W   36
#define IN_N   720          // 20*36
#define PIN    728
#define PMID   616
#define SMEM_FUSED ((8*PIN + 32*PMID)*4)   // 102144 bytes

__global__ __launch_bounds__(256) void fused_conv_kernel(const float* __restrict__ w1,
                                                         const float* __restrict__ b1,
                                                         const float* __restrict__ w2,
                                                         const float* __restrict__ b2)
{
    extern __shared__ unsigned dsm[];
    unsigned* sIn  = dsm;               // 8  x 728
    unsigned* sMid = dsm + 8*PIN;       // 32 x 616
    __shared__ float sB1[32];
    __shared__ float sB2[8];

    const int n  = blockIdx.z;
    const int X0 = blockIdx.x * FT_X;
    const int Y0 = blockIdx.y * FT_Y;
    const int tid  = threadIdx.x;
    const int lane = tid & 31, wid = tid >> 5;
    const int qr = lane >> 2, icb = lane & 3;

    if (tid < 32) sB1[tid] = b1[tid];
    if (tid < 8)  sB2[tid] = b2[tid];

    for (int i = tid; i < IN_N; i += 256) {
        int r = i / IN_W, c = i - r*IN_W;
        int gy = Y0 - 2 + r, gx = X0 - 2 + c;
        bool ok = (gy >= 0 && gy < Pn && gx >= 0 && gx < Pn);
        const float* base = g_S + (size_t)(n*8)*PP2 + (size_t)gy*Pn + gx;
        #pragma unroll
        for (int ic = 0; ic < 8; ic++) {
            float v = ok ? base[(size_t)ic*PP2] : 0.f;
            sIn[ic*PIN + i] = tf32_of(v);
        }
    }

    unsigned bf[9][4][2];
    #pragma unroll
    for (int s = 0; s < 9; s++)
        #pragma unroll
        for (int g = 0; g < 4; g++) {
            int oc = g*8 + qr;
            bf[s][g][0] = tf32_of(w1[(oc*8 + icb)*9 + s]);
            bf[s][g][1] = tf32_of(w1[(oc*8 + icb + 4)*9 + s]);
        }
    __syncthreads();

    for (int t = wid; t < 39; t += 8) {
        int pr0 = t*16 + qr;
        int pr1 = pr0 + 8;
        int q0 = pr0 < MID_N ? pr0 : MID_N - 1;
        int q1 = pr1 < MID_N ? pr1 : MID_N - 1;
        int my0 = q0 / MID_W, mx0 = q0 - my0*MID_W;
        int my1 = q1 / MID_W, mx1 = q1 - my1*MID_W;
        int base0 = my0*IN_W + mx0;
        int base1 = my1*IN_W + mx1;
        float acc[4][4] = {};
        #pragma unroll
        for (int ky = 0; ky < 3; ky++) {
            #pragma unroll
            for (int kx = 0; kx < 3; kx++) {
                int off = ky*IN_W + kx;
                unsigned a[4];
                a[0] = sIn[icb*PIN     + base0 + off];
                a[1] = sIn[icb*PIN     + base1 + off];
                a[2] = sIn[(icb+4)*PIN + base0 + off];
                a[3] = sIn[(icb+4)*PIN + base1 + off];
                int s = ky*3 + kx;
                #pragma unroll
                for (int g = 0; g < 4; g++) mma_tf32(acc[g], a, bf[s][g]);
            }
        }
        bool s0 = pr0 < MID_N, s1 = pr1 < MID_N;
        int gy0 = Y0 - 1 + my0, gx0 = X0 - 1 + mx0;
        int gy1 = Y0 - 1 + my1, gx1 = X0 - 1 + mx1;
        bool in0 = (gy0 >= 0 && gy0 < Pn && gx0 >= 0 && gx0 < Pn);
        bool in1 = (gy1 >= 0 && gy1 < Pn && gx1 >= 0 && gx1 < Pn);
        #pragma unroll
        for (int g = 0; g < 4; g++) {
            int oc = g*8 + 2*icb;
            if (s0) {
                float v0 = in0 ? fmaxf(acc[g][0] + sB1[oc],   0.f) : 0.f;
                float v1 = in0 ? fmaxf(acc[g][1] + sB1[oc+1], 0.f) : 0.f;
                sMid[oc*PMID + q0]     = tf32_of(v0);
                sMid[(oc+1)*PMID + q0] = tf32_of(v1);
            }
            if (s1) {
                float v2 = in1 ? fmaxf(acc[g][2] + sB1[oc],   0.f) : 0.f;
                float v3 = in1 ? fmaxf(acc[g][3] + sB1[oc+1], 0.f) : 0.f;
                sMid[oc*PMID + q1]     = tf32_of(v2);
                sMid[(oc+1)*PMID + q1] = tf32_of(v3);
            }
        }
    }
    __syncthreads();

    #pragma unroll
    for (int s = 0; s < 9; s++)
        #pragma unroll
        for (int kc = 0; kc < 4; kc++) {
            bf[s][kc][0] = tf32_of(w2[(qr*32 + kc*8 + icb)*9 + s]);
            bf[s][kc][1] = tf32_of(w2[(qr*32 + kc*8 + icb + 4)*9 + s]);
        }

    for (int t = wid; t < 32; t += 8) {
        int p0 = t*16 + qr;
        int p1 = p0 + 8;
        int oy0 = p0 >> 5, ox0 = p0 & 31;
        int oy1 = p1 >> 5, ox1 = p1 & 31;
        float acc[4] = {};
        #pragma unroll
        for (int ky = 0; ky < 3; ky++) {
            #pragma unroll
            for (int kx = 0; kx < 3; kx++) {
                int r0 = (oy0 + ky)*MID_W + ox0 + kx;
                int r1 = (oy1 + ky)*MID_W + ox1 + kx;
                int s = ky*3 + kx;
                #pragma unroll
                for (int kc = 0; kc < 4; kc++) {
                    unsigned a[4];
                    a[0] = sMid[(kc*8 + icb)*PMID     + r0];
                    a[1] = sMid[(kc*8 + icb)*PMID     + r1];
                    a[2] = sMid[(kc*8 + icb + 4)*PMID + r0];
                    a[3] = sMid[(kc*8 + icb + 4)*PMID + r1];
                    mma_tf32(acc, a, bf[s][kc]);
                }
            }
        }
        int oc = 2*icb;
        float bb0 = sB2[oc], bb1 = sB2[oc+1];
        int y0g = Y0 + oy0, x0g = X0 + ox0;
        int y1g = Y0 + oy1, x1g = X0 + ox1;
        if (y0g < Pn && x0g < Pn) {
            float* d = g_C1 + (size_t)(n*Hn + oc)*PP2 + (size_t)y0g*Pn + x0g;
            d[0]   = fmaxf(acc[0] + bb0, 0.f);
            d[PP2] = fmaxf(acc[1] + bb1, 0.f);
        }
        if (y1g < Pn && x1g < Pn) {
            float* d = g_C1 + (size_t)(n*Hn + oc)*PP2 + (size_t)y1g*Pn + x1g;
            d[0]   = fmaxf(acc[2] + bb0, 0.f);
            d[PP2] = fmaxf(acc[3] + bb1, 0.f);
        }
    }
}

// ============================================================
// K7: out[b,p] = mean_h sum_q attn2[b,h,p,q] * value[b,q]
// ============================================================
__global__ __launch_bounds__(256) void final_kernel(const float* __restrict__ value,
                                                    float* __restrict__ out)
{
    const int bp = blockIdx.x;
    const int b = bp / Pn, p = bp % Pn;
    const float* vrow = value + b*Pn;
    const int tid = threadIdx.x;
    float s = 0.f;
    #pragma unroll
    for (int h = 0; h < Hn; h++) {
        const float* ar = g_C1 + (size_t)(b*Hn + h)*PP2 + p*Pn;
        for (int q = tid; q < Pn; q += 256) s += ar[q] * vrow[q];
    }
    __shared__ float red[256];
    red[tid] = s; __syncthreads();
    for (int st = 128; st > 0; st >>= 1) { if (tid < st) red[tid] += red[tid+st]; __syncthreads(); }
    if (tid == 0) out[bp] = red[0] * 0.125f;
}

// ============================================================
extern "C" void kernel_launch(void* const* d_in, const int* in_sizes, int n_in,
                              void* d_out, int out_size)
{
    const float* query = (const float*)d_in[0];
    const float* key_t = (const float*)d_in[1];
    const float* value = (const float*)d_in[2];
    const float* Wq    = (const float*)d_in[3];
    const float* bq    = (const float*)d_in[4];
    const float* Wk    = (const float*)d_in[5];
    const float* bk    = (const float*)d_in[6];
    const float* c1w   = (const float*)d_in[7];
    const float* c1b   = (const float*)d_in[8];
    const float* c2w   = (const float*)d_in[9];
    const float* c2b   = (const float*)d_in[10];
    float* out = (float*)d_out;

    static int smem_set = 0;
    if (!smem_set) {
        cudaFuncSetAttribute(fused_conv_kernel,
                             cudaFuncAttributeMaxDynamicSharedMemorySize, SMEM_FUSED);
        cudaFuncSetAttribute(scores_kernel,
                             cudaFuncAttributeMaxDynamicSharedMemorySize, SC_SMEM);
        smem_set = 1;
    }

    proj_kernel<<<dim3(8, 57), 256>>>(query, Wq, bq, 0);
    proj_kernel<<<dim3(8, 57), 256>>>(key_t, Wk, bk, 1);
    scores_kernel<<<dim3(15, 15, 32), 256, SC_SMEM>>>();
    modsm_kernel<<<dim3(BHn*Pn), 256>>>();
    fused_conv_kernel<<<dim3(29, 57, 4), 256, SMEM_FUSED>>>(c1w, c1b, c2w, c2b);
    final_kernel<<<dim3(Bn*Pn), 256>>>(value, out);
}

// round 10
// speedup vs baseline: 2.3975x; 1.1459x over previous
#include <cuda_runtime.h>
#include <cuda_bf16.h>

#define Bn   4
#define Pn   900
#define Hn   8
#define DKn  64
#define DMn  512
#define PP2  (Pn*Pn)      // 810000
#define BHn  (Bn*Hn)      // 32

typedef unsigned long long u64_t;

// ---- tf32 tensor-core helpers ----
__device__ __forceinline__ unsigned tf32_of(float f) {
    unsigned u;
    asm("cvt.rna.tf32.f32 %0, %1;" : "=r"(u) : "f"(f));
    return u;
}
__device__ __forceinline__ void mma_tf32(float* c, const unsigned* a, const unsigned* b) {
    asm("mma.sync.aligned.m16n8k8.row.col.f32.tf32.tf32.f32 "
        "{%0,%1,%2,%3}, {%4,%5,%6,%7}, {%8,%9}, {%0,%1,%2,%3};"
        : "+f"(c[0]), "+f"(c[1]), "+f"(c[2]), "+f"(c[3])
        : "r"(a[0]), "r"(a[1]), "r"(a[2]), "r"(a[3]), "r"(b[0]), "r"(b[1]));
}

// order-preserving float->uint
__device__ __forceinline__ unsigned ord_f(float v) {
    unsigned b = __float_as_uint(v);
    return (b & 0x80000000u) ? ~b : (b | 0x80000000u);
}
__device__ __forceinline__ u64_t amax_key(float v, int p) {
    return ((u64_t)ord_f(v) << 32) | (u64_t)(0xFFFFFFFFu - (unsigned)p);
}

// ---- scratch (static device allocations; no runtime alloc) ----
__device__ float g_QP[Bn*Hn*Pn*DKn];        // [b,h,p,c]
__device__ float g_KP[Bn*Hn*Pn*DKn];        // [b,h,p,c]
__device__ float g_S [BHn*PP2];             // scores -> attn (conv input)
__device__ u64_t g_AMX[BHn*Pn];             // packed (value, ~p) argmax keys
__device__ float g_PART[Bn*Hn*Pn*64];       // conv2+einsum partials [b,h,p,xp]

// ============================================================
// K1: projection GEMM, tf32 3-MMA split precision.
// out[b,h,p,c] = sum_k A[m,k]*W[n,k] + bias.  M=3600,N=512,K=512.
// Block 64m x 64n, warp = m16 x n32, K staged 32 at a time.
// ============================================================
__global__ __launch_bounds__(256) void proj_kernel(const float* __restrict__ A,
                                                   const float* __restrict__ W,
                                                   const float* __restrict__ bias,
                                                   int which)
{
    __shared__ unsigned Ahi[64*36], Alo[64*36], Whi[64*36], Wlo[64*36];
    float* out = which ? g_KP : g_QP;
    const int bm = blockIdx.y * 64;
    const int bn = blockIdx.x * 64;
    const int tid = threadIdx.x;
    const int lane = tid & 31, wid = tid >> 5;
    const int qr = lane >> 2, icb = lane & 3;
    const int m0 = (wid & 3) * 16;
    const int n0 = (wid >> 2) * 32;
    float acc[4][4] = {};

    for (int k0 = 0; k0 < DMn; k0 += 32) {
        #pragma unroll
        for (int i = tid; i < 2048; i += 256) {
            int r = i >> 5, kk = i & 31;
            int m = bm + r;
            float av = (m < Bn*Pn) ? A[(size_t)m*DMn + k0 + kk] : 0.f;
            float wv = W[(size_t)(bn + r)*DMn + k0 + kk];
            unsigned ah = tf32_of(av), wh = tf32_of(wv);
            Ahi[r*36 + kk] = ah;
            Alo[r*36 + kk] = tf32_of(av - __uint_as_float(ah));
            Whi[r*36 + kk] = wh;
            Wlo[r*36 + kk] = tf32_of(wv - __uint_as_float(wh));
        }
        __syncthreads();
        #pragma unroll
        for (int ks = 0; ks < 4; ks++) {
            int k8 = ks*8;
            unsigned ah[4], al[4];
            int rA = (m0 + qr)*36 + k8 + icb;
            int rB = (m0 + qr + 8)*36 + k8 + icb;
            ah[0] = Ahi[rA];     ah[1] = Ahi[rB];
            ah[2] = Ahi[rA + 4]; ah[3] = Ahi[rB + 4];
            al[0] = Alo[rA];     al[1] = Alo[rB];
            al[2] = Alo[rA + 4]; al[3] = Alo[rB + 4];
            #pragma unroll
            for (int j = 0; j < 4; j++) {
                int rK = (n0 + j*8 + qr)*36 + k8 + icb;
                unsigned bh_[2] = { Whi[rK], Whi[rK + 4] };
                unsigned bl_[2] = { Wlo[rK], Wlo[rK + 4] };
                mma_tf32(acc[j], ah, bh_);
                mma_tf32(acc[j], ah, bl_);
                mma_tf32(acc[j], al, bh_);
            }
        }
        __syncthreads();
    }

    const int mA = bm + m0 + qr, mB = mA + 8;
    #pragma unroll
    for (int j = 0; j < 4; j++) {
        int na = bn + n0 + j*8 + 2*icb, nb2 = na + 1;
        if (mA < Bn*Pn) {
            int b = mA / Pn, p = mA % Pn;
            out[((b*Hn + (na  >> 6))*Pn + p)*DKn + (na  & 63)] = acc[j][0] + bias[na];
            out[((b*Hn + (nb2 >> 6))*Pn + p)*DKn + (nb2 & 63)] = acc[j][1] + bias[nb2];
        }
        if (mB < Bn*Pn) {
            int b = mB / Pn, p = mB % Pn;
            out[((b*Hn + (na  >> 6))*Pn + p)*DKn + (na  & 63)] = acc[j][2] + bias[na];
            out[((b*Hn + (nb2 >> 6))*Pn + p)*DKn + (nb2 & 63)] = acc[j][3] + bias[nb2];
        }
    }
}

// ============================================================
// K2: scores via tf32 3-MMA split precision + fused argmax.
// ============================================================
#define SC_SMEM (4*64*68*4)     // 69632 B

__global__ __launch_bounds__(256) void scores_kernel()
{
    extern __shared__ unsigned sc[];
    unsigned* Qhi = sc;
    unsigned* Qlo = sc + 64*68;
    unsigned* Khi = sc + 2*64*68;
    unsigned* Klo = sc + 3*64*68;

    const int bh = blockIdx.z;
    const float* Q = g_QP + bh*Pn*DKn;
    const float* K = g_KP + bh*Pn*DKn;
    const int p0 = blockIdx.y*64, q0 = blockIdx.x*64;
    const int tid = threadIdx.x;
    const int lane = tid & 31, wid = tid >> 5;
    const int qr = lane >> 2, icb = lane & 3;

    #pragma unroll
    for (int i = 0; i < 16; i++) {
        int idx = tid + i*256;
        int r = idx >> 6, c = idx & 63;
        float qv = (p0 + r < Pn) ? Q[(p0+r)*DKn + c] : 0.f;
        float kv = (q0 + r < Pn) ? K[(q0+r)*DKn + c] : 0.f;
        unsigned qh = tf32_of(qv);
        unsigned kh = tf32_of(kv);
        Qhi[r*68 + c] = qh;
        Qlo[r*68 + c] = tf32_of(qv - __uint_as_float(qh));
        Khi[r*68 + c] = kh;
        Klo[r*68 + c] = tf32_of(kv - __uint_as_float(kh));
    }
    __syncthreads();

    const int m0 = (wid & 3) * 16;
    const int n0 = (wid >> 2) * 32;
    float acc[4][4] = {};

    #pragma unroll
    for (int ks = 0; ks < 8; ks++) {
        int k0 = ks*8;
        unsigned ah[4], al[4];
        int rA = (m0 + qr)*68 + k0 + icb;
        int rB = (m0 + qr + 8)*68 + k0 + icb;
        ah[0] = Qhi[rA];     ah[1] = Qhi[rB];
        ah[2] = Qhi[rA + 4]; ah[3] = Qhi[rB + 4];
        al[0] = Qlo[rA];     al[1] = Qlo[rB];
        al[2] = Qlo[rA + 4]; al[3] = Qlo[rB + 4];
        #pragma unroll
        for (int j = 0; j < 4; j++) {
            int rK = (n0 + j*8 + qr)*68 + k0 + icb;
            unsigned bh_[2] = { Khi[rK], Khi[rK + 4] };
            unsigned bl_[2] = { Klo[rK], Klo[rK + 4] };
            mma_tf32(acc[j], ah, bh_);
            mma_tf32(acc[j], ah, bl_);
            mma_tf32(acc[j], al, bh_);
        }
    }

    float* Sb = g_S + bh*PP2;
    const int pA = p0 + m0 + qr, pB = pA + 8;
    const bool vA = pA < Pn, vB = pB < Pn;
    #pragma unroll
    for (int j = 0; j < 4; j++) {
        int qa = q0 + n0 + j*8 + 2*icb;
        int qb = qa + 1;
        if (vA) {
            if (qa < Pn) Sb[pA*Pn + qa] = acc[j][0];
            if (qb < Pn) Sb[pA*Pn + qb] = acc[j][1];
        }
        if (vB) {
            if (qa < Pn) Sb[pB*Pn + qa] = acc[j][2];
            if (qb < Pn) Sb[pB*Pn + qb] = acc[j][3];
        }
        u64_t ka = 0, kb = 0;
        if (vA) { ka = amax_key(acc[j][0], pA); kb = amax_key(acc[j][1], pA); }
        if (vB) {
            u64_t t = amax_key(acc[j][2], pB); if (t > ka) ka = t;
            t = amax_key(acc[j][3], pB);       if (t > kb) kb = t;
        }
        #pragma unroll
        for (int m = 4; m <= 16; m <<= 1) {
            u64_t ta = __shfl_xor_sync(0xFFFFFFFFu, ka, m);
            u64_t tb = __shfl_xor_sync(0xFFFFFFFFu, kb, m);
            if (ta > ka) ka = ta;
            if (tb > kb) kb = tb;
        }
        if (qr == 0) {
            if (qa < Pn) atomicMax(&g_AMX[bh*Pn + qa], ka);
            if (qb < Pn) atomicMax(&g_AMX[bh*Pn + qb], kb);
        }
    }
}

// ============================================================
// K4: gaussian (separable table) + scale + softmax; warp-per-row.
// Block = 8 rows of one bh; table + decoded argmax staged in smem.
// ============================================================
__global__ __launch_bounds__(256) void modsm_kernel()
{
    __shared__ float sT[900];            // T[a][b] = exp(-(lin(a)-b)^2 * 0.02)
    __shared__ unsigned char sFX[900], sFY[900];
    const int bh = blockIdx.y;
    const int p0 = blockIdx.x * 8;
    const int tid = threadIdx.x, lane = tid & 31, wrp = tid >> 5;

    for (int i = tid; i < 900; i += 256) {
        int a = i / 30, bc = i - (i/30)*30;
        float d = (-1.f + (2.f/29.f)*(float)a) - (float)bc;
        sT[i] = __expf(-d*d*0.02f);
        unsigned id = 0xFFFFFFFFu - (unsigned)(g_AMX[bh*Pn + i] & 0xFFFFFFFFu);
        sFX[i] = (unsigned char)(id % 30);
        sFY[i] = (unsigned char)(id / 30);
    }
    __syncthreads();

    const int p = p0 + wrp;
    if (p >= Pn) return;
    float* Srow = g_S + (size_t)bh*PP2 + (size_t)p*Pn;
    const float* Tx = sT + (p % 30)*30;
    const float* Ty = sT + (p / 30)*30;

    float v[29];
    float lmax = -1e30f;
    #pragma unroll
    for (int i = 0; i < 29; i++) {
        int q = lane + i*32;
        if (q < Pn) {
            float g = Tx[sFX[q]] * Ty[sFY[q]];
            v[i] = g * Srow[q] * 0.125f;
            lmax = fmaxf(lmax, v[i]);
        } else v[i] = -1e30f;
    }
    #pragma unroll
    for (int m = 16; m > 0; m >>= 1)
        lmax = fmaxf(lmax, __shfl_xor_sync(0xFFFFFFFFu, lmax, m));

    float lsum = 0.f;
    #pragma unroll
    for (int i = 0; i < 29; i++) {
        float e = __expf(v[i] - lmax);
        v[i] = e;
        if (lane + i*32 < Pn) lsum += e;
    }
    #pragma unroll
    for (int m = 16; m > 0; m >>= 1)
        lsum += __shfl_xor_sync(0xFFFFFFFFu, lsum, m);
    const float inv = 1.f / lsum;
    #pragma unroll
    for (int i = 0; i < 29; i++) {
        int q = lane + i*32;
        if (q < Pn) Srow[q] = v[i] * inv;
    }
}

// ============================================================
// K5: FUSED conv1+conv2+value-einsum, tf32 MMA.
// conv2 output never hits DRAM: relu(out)*value[b,x] reduced over the
// 16-x warp-tile, one partial per (b,oc,y,xhalf) -> g_PART.
// ============================================================
#define FT_Y   16
#define FT_X   32
#define MID_W  34
#define MID_N  612
#define IN_W   36
#define IN_N   720
#define PIN    728
#define PMID   616
#define SMEM_FUSED ((8*PIN + 32*PMID)*4)   // 102144 bytes

__global__ __launch_bounds__(256) void fused_conv_kernel(const float* __restrict__ w1,
                                                         const float* __restrict__ b1,
                                                         const float* __restrict__ w2,
                                                         const float* __restrict__ b2,
                                                         const float* __restrict__ value)
{
    extern __shared__ unsigned dsm[];
    unsigned* sIn  = dsm;               // 8  x 728
    unsigned* sMid = dsm + 8*PIN;       // 32 x 616
    __shared__ float sB1[32];
    __shared__ float sB2[8];
    __shared__ float sVal[32];

    const int n  = blockIdx.z;
    const int X0 = blockIdx.x * FT_X;
    const int Y0 = blockIdx.y * FT_Y;
    const int tid  = threadIdx.x;
    const int lane = tid & 31, wid = tid >> 5;
    const int qr = lane >> 2, icb = lane & 3;

    if (tid < 32) {
        sB1[tid] = b1[tid];
        sVal[tid] = (X0 + tid < Pn) ? value[n*Pn + X0 + tid] : 0.f;
    }
    if (tid < 8)  sB2[tid] = b2[tid];

    for (int i = tid; i < IN_N; i += 256) {
        int r = i / IN_W, c = i - r*IN_W;
        int gy = Y0 - 2 + r, gx = X0 - 2 + c;
        bool ok = (gy >= 0 && gy < Pn && gx >= 0 && gx < Pn);
        const float* base = g_S + (size_t)(n*8)*PP2 + (size_t)gy*Pn + gx;
        #pragma unroll
        for (int ic = 0; ic < 8; ic++) {
            float v = ok ? base[(size_t)ic*PP2] : 0.f;
            sIn[ic*PIN + i] = tf32_of(v);
        }
    }

    unsigned bf[9][4][2];
    #pragma unroll
    for (int s = 0; s < 9; s++)
        #pragma unroll
        for (int g = 0; g < 4; g++) {
            int oc = g*8 + qr;
            bf[s][g][0] = tf32_of(w1[(oc*8 + icb)*9 + s]);
            bf[s][g][1] = tf32_of(w1[(oc*8 + icb + 4)*9 + s]);
        }
    __syncthreads();

    // ---- phase 1: conv1 -> sMid ----
    for (int t = wid; t < 39; t += 8) {
        int pr0 = t*16 + qr;
        int pr1 = pr0 + 8;
        int q0 = pr0 < MID_N ? pr0 : MID_N - 1;
        int q1 = pr1 < MID_N ? pr1 : MID_N - 1;
        int my0 = q0 / MID_W, mx0 = q0 - my0*MID_W;
        int my1 = q1 / MID_W, mx1 = q1 - my1*MID_W;
        int base0 = my0*IN_W + mx0;
        int base1 = my1*IN_W + mx1;
        float acc[4][4] = {};
        #pragma unroll
        for (int ky = 0; ky < 3; ky++) {
            #pragma unroll
            for (int kx = 0; kx < 3; kx++) {
                int off = ky*IN_W + kx;
                unsigned a[4];
                a[0] = sIn[icb*PIN     + base0 + off];
                a[1] = sIn[icb*PIN     + base1 + off];
                a[2] = sIn[(icb+4)*PIN + base0 + off];
                a[3] = sIn[(icb+4)*PIN + base1 + off];
                int s = ky*3 + kx;
                #pragma unroll
                for (int g = 0; g < 4; g++) mma_tf32(acc[g], a, bf[s][g]);
            }
        }
        bool s0 = pr0 < MID_N, s1 = pr1 < MID_N;
        int gy0 = Y0 - 1 + my0, gx0 = X0 - 1 + mx0;
        int gy1 = Y0 - 1 + my1, gx1 = X0 - 1 + mx1;
        bool in0 = (gy0 >= 0 && gy0 < Pn && gx0 >= 0 && gx0 < Pn);
        bool in1 = (gy1 >= 0 && gy1 < Pn && gx1 >= 0 && gx1 < Pn);
        #pragma unroll
        for (int g = 0; g < 4; g++) {
            int oc = g*8 + 2*icb;
            if (s0) {
                float v0 = in0 ? fmaxf(acc[g][0] + sB1[oc],   0.f) : 0.f;
                float v1 = in0 ? fmaxf(acc[g][1] + sB1[oc+1], 0.f) : 0.f;
                sMid[oc*PMID + q0]     = tf32_of(v0);
                sMid[(oc+1)*PMID + q0] = tf32_of(v1);
            }
            if (s1) {
                float v2 = in1 ? fmaxf(acc[g][2] + sB1[oc],   0.f) : 0.f;
                float v3 = in1 ? fmaxf(acc[g][3] + sB1[oc+1], 0.f) : 0.f;
                sMid[oc*PMID + q1]     = tf32_of(v2);
                sMid[(oc+1)*PMID + q1] = tf32_of(v3);
            }
        }
    }
    __syncthreads();

    #pragma unroll
    for (int s = 0; s < 9; s++)
        #pragma unroll
        for (int kc = 0; kc < 4; kc++) {
            bf[s][kc][0] = tf32_of(w2[(qr*32 + kc*8 + icb)*9 + s]);
            bf[s][kc][1] = tf32_of(w2[(qr*32 + kc*8 + icb + 4)*9 + s]);
        }

    // ---- phase 2: conv2 + value reduction -> g_PART ----
    for (int t = wid; t < 32; t += 8) {
        int p0 = t*16 + qr;
        int p1 = p0 + 8;
        int oy = t >> 1;                     // warp-tile = one y row
        int ox0 = (t & 1)*16 + qr, ox1 = ox0 + 8;
        float acc[4] = {};
        #pragma unroll
        for (int ky = 0; ky < 3; ky++) {
            #pragma unroll
            for (int kx = 0; kx < 3; kx++) {
                int r0 = (oy + ky)*MID_W + ox0 + kx;
                int r1 = (oy + ky)*MID_W + ox1 + kx;
                int s = ky*3 + kx;
                #pragma unroll
                for (int kc = 0; kc < 4; kc++) {
                    unsigned a[4];
                    a[0] = sMid[(kc*8 + icb)*PMID     + r0];
                    a[1] = sMid[(kc*8 + icb)*PMID     + r1];
                    a[2] = sMid[(kc*8 + icb + 4)*PMID + r0];
                    a[3] = sMid[(kc*8 + icb + 4)*PMID + r1];
                    mma_tf32(acc, a, bf[s][kc]);
                }
            }
        }
        int oc = 2*icb;
        float bb0 = sB2[oc], bb1 = sB2[oc+1];
        float svA = sVal[ox0], svB = sVal[ox1];
        float r0 = fmaxf(acc[0] + bb0, 0.f);
        float r1 = fmaxf(acc[1] + bb1, 0.f);
        float r2 = fmaxf(acc[2] + bb0, 0.f);
        float r3 = fmaxf(acc[3] + bb1, 0.f);
        float s0 = r0*svA + r2*svB;
        float s1 = r1*svA + r3*svB;
        #pragma unroll
        for (int m = 4; m <= 16; m <<= 1) {
            s0 += __shfl_xor_sync(0xFFFFFFFFu, s0, m);
            s1 += __shfl_xor_sync(0xFFFFFFFFu, s1, m);
        }
        int y = Y0 + oy;
        if (qr == 0 && y < Pn) {
            int xp = blockIdx.x*2 + (t & 1);
            g_PART[((size_t)(n*Hn + oc    )*Pn + y)*64 + xp] = s0;
            g_PART[((size_t)(n*Hn + oc + 1)*Pn + y)*64 + xp] = s1;
        }
        (void)p0; (void)p1;
    }
}

// ============================================================
// K6: reduce partials -> out[b,p] = mean_h sum_xp
// ============================================================
__global__ __launch_bounds__(128) void reduce_kernel(float* __restrict__ out)
{
    const int bp = blockIdx.x;
    const int b = bp / Pn, p = bp % Pn;
    const int tid = threadIdx.x;
    float s = 0.f;
    for (int i = tid; i < 512; i += 128) {
        int h = i >> 6, xp = i & 63;
        if (xp < 58)
            s += g_PART[((size_t)(b*Hn + h)*Pn + p)*64 + xp];
    }
    __shared__ float red[128];
    red[tid] = s; __syncthreads();
    for (int st = 64; st > 0; st >>= 1) {
        if (tid < st) red[tid] += red[tid + st];
        __syncthreads();
    }
    if (tid == 0) out[bp] = red[0] * 0.125f;
}

// ============================================================
extern "C" void kernel_launch(void* const* d_in, const int* in_sizes, int n_in,
                              void* d_out, int out_size)
{
    const float* query = (const float*)d_in[0];
    const float* key_t = (const float*)d_in[1];
    const float* value = (const float*)d_in[2];
    const float* Wq    = (const float*)d_in[3];
    const float* bq    = (const float*)d_in[4];
    const float* Wk    = (const float*)d_in[5];
    const float* bk    = (const float*)d_in[6];
    const float* c1w   = (const float*)d_in[7];
    const float* c1b   = (const float*)d_in[8];
    const float* c2w   = (const float*)d_in[9];
    const float* c2b   = (const float*)d_in[10];
    float* out = (float*)d_out;

    static int smem_set = 0;
    if (!smem_set) {
        cudaFuncSetAttribute(fused_conv_kernel,
                             cudaFuncAttributeMaxDynamicSharedMemorySize, SMEM_FUSED);
        cudaFuncSetAttribute(scores_kernel,
                             cudaFuncAttributeMaxDynamicSharedMemorySize, SC_SMEM);
        smem_set = 1;
    }

    proj_kernel<<<dim3(8, 57), 256>>>(query, Wq, bq, 0);
    proj_kernel<<<dim3(8, 57), 256>>>(key_t, Wk, bk, 1);
    scores_kernel<<<dim3(15, 15, 32), 256, SC_SMEM>>>();
    modsm_kernel<<<dim3(113, 32), 256>>>();
    fused_conv_kernel<<<dim3(29, 57, 4), 256, SMEM_FUSED>>>(c1w, c1b, c2w, c2b, value);
    reduce_kernel<<<dim3(Bn*Pn), 128>>>(out);
}

// round 11
// speedup vs baseline: 2.9950x; 1.2492x over previous
#include <cuda_runtime.h>
#include <cuda_bf16.h>
#include <cuda_fp16.h>

#define Bn   4
#define Pn   900
#define Hn   8
#define DKn  64
#define DMn  512
#define PP2  (Pn*Pn)      // 810000
#define BHn  (Bn*Hn)      // 32

typedef unsigned long long u64_t;

// ---- tf32 tensor-core helpers ----
__device__ __forceinline__ unsigned tf32_of(float f) {
    unsigned u;
    asm("cvt.rna.tf32.f32 %0, %1;" : "=r"(u) : "f"(f));
    return u;
}
__device__ __forceinline__ void mma_tf32(float* c, const unsigned* a, const unsigned* b) {
    asm("mma.sync.aligned.m16n8k8.row.col.f32.tf32.tf32.f32 "
        "{%0,%1,%2,%3}, {%4,%5,%6,%7}, {%8,%9}, {%0,%1,%2,%3};"
        : "+f"(c[0]), "+f"(c[1]), "+f"(c[2]), "+f"(c[3])
        : "r"(a[0]), "r"(a[1]), "r"(a[2]), "r"(a[3]), "r"(b[0]), "r"(b[1]));
}

// ---- fp16 m16n8k16 (same 10-bit mantissa as tf32, 2x MAC/instr) ----
__device__ __forceinline__ void mma_f16_k16(float* c, const unsigned* a, const unsigned* b) {
    asm("mma.sync.aligned.m16n8k16.row.col.f32.f16.f16.f32 "
        "{%0,%1,%2,%3}, {%4,%5,%6,%7}, {%8,%9}, {%0,%1,%2,%3};"
        : "+f"(c[0]), "+f"(c[1]), "+f"(c[2]), "+f"(c[3])
        : "r"(a[0]), "r"(a[1]), "r"(a[2]), "r"(a[3]), "r"(b[0]), "r"(b[1]));
}
__device__ __forceinline__ unsigned packh2(float x, float y) {
    __half2 h = __floats2half2_rn(x, y);
    return *reinterpret_cast<unsigned*>(&h);
}

// order-preserving float->uint
__device__ __forceinline__ unsigned ord_f(float v) {
    unsigned b = __float_as_uint(v);
    return (b & 0x80000000u) ? ~b : (b | 0x80000000u);
}
__device__ __forceinline__ u64_t amax_key(float v, int p) {
    return ((u64_t)ord_f(v) << 32) | (u64_t)(0xFFFFFFFFu - (unsigned)p);
}

// ---- scratch (static device allocations; no runtime alloc) ----
__device__ float g_QP[Bn*Hn*Pn*DKn];        // [b,h,p,c]
__device__ float g_KP[Bn*Hn*Pn*DKn];        // [b,h,p,c]
__device__ float g_S [BHn*PP2];             // scores -> attn (conv input)
__device__ u64_t g_AMX[BHn*Pn];             // packed (value, ~p) argmax keys
__device__ float g_PART[Bn*Hn*Pn*64];       // conv2+einsum partials [b,h,p,xp]

// ============================================================
// K1: projection GEMM, tf32 3-MMA split precision.
// ============================================================
__global__ __launch_bounds__(256) void proj_kernel(const float* __restrict__ A,
                                                   const float* __restrict__ W,
                                                   const float* __restrict__ bias,
                                                   int which)
{
    __shared__ unsigned Ahi[64*36], Alo[64*36], Whi[64*36], Wlo[64*36];
    float* out = which ? g_KP : g_QP;
    const int bm = blockIdx.y * 64;
    const int bn = blockIdx.x * 64;
    const int tid = threadIdx.x;
    const int lane = tid & 31, wid = tid >> 5;
    const int qr = lane >> 2, icb = lane & 3;
    const int m0 = (wid & 3) * 16;
    const int n0 = (wid >> 2) * 32;
    float acc[4][4] = {};

    for (int k0 = 0; k0 < DMn; k0 += 32) {
        #pragma unroll
        for (int i = tid; i < 2048; i += 256) {
            int r = i >> 5, kk = i & 31;
            int m = bm + r;
            float av = (m < Bn*Pn) ? A[(size_t)m*DMn + k0 + kk] : 0.f;
            float wv = W[(size_t)(bn + r)*DMn + k0 + kk];
            unsigned ah = tf32_of(av), wh = tf32_of(wv);
            Ahi[r*36 + kk] = ah;
            Alo[r*36 + kk] = tf32_of(av - __uint_as_float(ah));
            Whi[r*36 + kk] = wh;
            Wlo[r*36 + kk] = tf32_of(wv - __uint_as_float(wh));
        }
        __syncthreads();
        #pragma unroll
        for (int ks = 0; ks < 4; ks++) {
            int k8 = ks*8;
            unsigned ah[4], al[4];
            int rA = (m0 + qr)*36 + k8 + icb;
            int rB = (m0 + qr + 8)*36 + k8 + icb;
            ah[0] = Ahi[rA];     ah[1] = Ahi[rB];
            ah[2] = Ahi[rA + 4]; ah[3] = Ahi[rB + 4];
            al[0] = Alo[rA];     al[1] = Alo[rB];
            al[2] = Alo[rA + 4]; al[3] = Alo[rB + 4];
            #pragma unroll
            for (int j = 0; j < 4; j++) {
                int rK = (n0 + j*8 + qr)*36 + k8 + icb;
                unsigned bh_[2] = { Whi[rK], Whi[rK + 4] };
                unsigned bl_[2] = { Wlo[rK], Wlo[rK + 4] };
                mma_tf32(acc[j], ah, bh_);
                mma_tf32(acc[j], ah, bl_);
                mma_tf32(acc[j], al, bh_);
            }
        }
        __syncthreads();
    }

    const int mA = bm + m0 + qr, mB = mA + 8;
    #pragma unroll
    for (int j = 0; j < 4; j++) {
        int na = bn + n0 + j*8 + 2*icb, nb2 = na + 1;
        if (mA < Bn*Pn) {
            int b = mA / Pn, p = mA % Pn;
            out[((b*Hn + (na  >> 6))*Pn + p)*DKn + (na  & 63)] = acc[j][0] + bias[na];
            out[((b*Hn + (nb2 >> 6))*Pn + p)*DKn + (nb2 & 63)] = acc[j][1] + bias[nb2];
        }
        if (mB < Bn*Pn) {
            int b = mB / Pn, p = mB % Pn;
            out[((b*Hn + (na  >> 6))*Pn + p)*DKn + (na  & 63)] = acc[j][2] + bias[na];
            out[((b*Hn + (nb2 >> 6))*Pn + p)*DKn + (nb2 & 63)] = acc[j][3] + bias[nb2];
        }
    }
}

// ============================================================
// K2: scores via tf32 3-MMA split precision + fused argmax.
// ============================================================
#define SC_SMEM (4*64*68*4)     // 69632 B

__global__ __launch_bounds__(256) void scores_kernel()
{
    extern __shared__ unsigned sc[];
    unsigned* Qhi = sc;
    unsigned* Qlo = sc + 64*68;
    unsigned* Khi = sc + 2*64*68;
    unsigned* Klo = sc + 3*64*68;

    const int bh = blockIdx.z;
    const float* Q = g_QP + bh*Pn*DKn;
    const float* K = g_KP + bh*Pn*DKn;
    const int p0 = blockIdx.y*64, q0 = blockIdx.x*64;
    const int tid = threadIdx.x;
    const int lane = tid & 31, wid = tid >> 5;
    const int qr = lane >> 2, icb = lane & 3;

    #pragma unroll
    for (int i = 0; i < 16; i++) {
        int idx = tid + i*256;
        int r = idx >> 6, c = idx & 63;
        float qv = (p0 + r < Pn) ? Q[(p0+r)*DKn + c] : 0.f;
        float kv = (q0 + r < Pn) ? K[(q0+r)*DKn + c] : 0.f;
        unsigned qh = tf32_of(qv);
        unsigned kh = tf32_of(kv);
        Qhi[r*68 + c] = qh;
        Qlo[r*68 + c] = tf32_of(qv - __uint_as_float(qh));
        Khi[r*68 + c] = kh;
        Klo[r*68 + c] = tf32_of(kv - __uint_as_float(kh));
    }
    __syncthreads();

    const int m0 = (wid & 3) * 16;
    const int n0 = (wid >> 2) * 32;
    float acc[4][4] = {};

    #pragma unroll
    for (int ks = 0; ks < 8; ks++) {
        int k0 = ks*8;
        unsigned ah[4], al[4];
        int rA = (m0 + qr)*68 + k0 + icb;
        int rB = (m0 + qr + 8)*68 + k0 + icb;
        ah[0] = Qhi[rA];     ah[1] = Qhi[rB];
        ah[2] = Qhi[rA + 4]; ah[3] = Qhi[rB + 4];
        al[0] = Qlo[rA];     al[1] = Qlo[rB];
        al[2] = Qlo[rA + 4]; al[3] = Qlo[rB + 4];
        #pragma unroll
        for (int j = 0; j < 4; j++) {
            int rK = (n0 + j*8 + qr)*68 + k0 + icb;
            unsigned bh_[2] = { Khi[rK], Khi[rK + 4] };
            unsigned bl_[2] = { Klo[rK], Klo[rK + 4] };
            mma_tf32(acc[j], ah, bh_);
            mma_tf32(acc[j], ah, bl_);
            mma_tf32(acc[j], al, bh_);
        }
    }

    float* Sb = g_S + bh*PP2;
    const int pA = p0 + m0 + qr, pB = pA + 8;
    const bool vA = pA < Pn, vB = pB < Pn;
    #pragma unroll
    for (int j = 0; j < 4; j++) {
        int qa = q0 + n0 + j*8 + 2*icb;
        int qb = qa + 1;
        if (vA) {
            if (qa < Pn) Sb[pA*Pn + qa] = acc[j][0];
            if (qb < Pn) Sb[pA*Pn + qb] = acc[j][1];
        }
        if (vB) {
            if (qa < Pn) Sb[pB*Pn + qa] = acc[j][2];
            if (qb < Pn) Sb[pB*Pn + qb] = acc[j][3];
        }
        u64_t ka = 0, kb = 0;
        if (vA) { ka = amax_key(acc[j][0], pA); kb = amax_key(acc[j][1], pA); }
        if (vB) {
            u64_t t = amax_key(acc[j][2], pB); if (t > ka) ka = t;
            t = amax_key(acc[j][3], pB);       if (t > kb) kb = t;
        }
        #pragma unroll
        for (int m = 4; m <= 16; m <<= 1) {
            u64_t ta = __shfl_xor_sync(0xFFFFFFFFu, ka, m);
            u64_t tb = __shfl_xor_sync(0xFFFFFFFFu, kb, m);
            if (ta > ka) ka = ta;
            if (tb > kb) kb = tb;
        }
        if (qr == 0) {
            if (qa < Pn) atomicMax(&g_AMX[bh*Pn + qa], ka);
            if (qb < Pn) atomicMax(&g_AMX[bh*Pn + qb], kb);
        }
    }
}

// ============================================================
// K4: gaussian (separable table) + scale + softmax; warp-per-row.
// ============================================================
__global__ __launch_bounds__(256) void modsm_kernel()
{
    __shared__ float sT[900];
    __shared__ unsigned char sFX[900], sFY[900];
    const int bh = blockIdx.y;
    const int p0 = blockIdx.x * 8;
    const int tid = threadIdx.x, lane = tid & 31, wrp = tid >> 5;

    for (int i = tid; i < 900; i += 256) {
        int a = i / 30, bc = i - (i/30)*30;
        float d = (-1.f + (2.f/29.f)*(float)a) - (float)bc;
        sT[i] = __expf(-d*d*0.02f);
        unsigned id = 0xFFFFFFFFu - (unsigned)(g_AMX[bh*Pn + i] & 0xFFFFFFFFu);
        sFX[i] = (unsigned char)(id % 30);
        sFY[i] = (unsigned char)(id / 30);
    }
    __syncthreads();

    const int p = p0 + wrp;
    if (p >= Pn) return;
    float* Srow = g_S + (size_t)bh*PP2 + (size_t)p*Pn;
    const float* Tx = sT + (p % 30)*30;
    const float* Ty = sT + (p / 30)*30;

    float v[29];
    float lmax = -1e30f;
    #pragma unroll
    for (int i = 0; i < 29; i++) {
        int q = lane + i*32;
        if (q < Pn) {
            float g = Tx[sFX[q]] * Ty[sFY[q]];
            v[i] = g * Srow[q] * 0.125f;
            lmax = fmaxf(lmax, v[i]);
        } else v[i] = -1e30f;
    }
    #pragma unroll
    for (int m = 16; m > 0; m >>= 1)
        lmax = fmaxf(lmax, __shfl_xor_sync(0xFFFFFFFFu, lmax, m));

    float lsum = 0.f;
    #pragma unroll
    for (int i = 0; i < 29; i++) {
        float e = __expf(v[i] - lmax);
        v[i] = e;
        if (lane + i*32 < Pn) lsum += e;
    }
    #pragma unroll
    for (int m = 16; m > 0; m >>= 1)
        lsum += __shfl_xor_sync(0xFFFFFFFFu, lsum, m);
    const float inv = 1.f / lsum;
    #pragma unroll
    for (int i = 0; i < 29; i++) {
        int q = lane + i*32;
        if (q < Pn) Srow[q] = v[i] * inv;
    }
}

// ============================================================
// K5: FUSED conv1+conv2+value-einsum, fp16 m16n8k16 MMA.
// Data packed as half2 ic-pairs in smem (conflict-free strides).
// conv1: K16 = 8ic @ shift sA || 8ic @ shift sB (5 pairs, 10th zero).
// conv2: K16 = 2 ic-octets of same shift (9 shifts x 2 chunks).
// ============================================================
#define FT_Y   16
#define FT_X   32
#define MID_W  34
#define MID_N  612
#define IN_W   36
#define IN_N   720
#define PIN    728
#define PMID   616
#define SMEM_FUSED ((4*PIN + 16*PMID)*4)   // 51136 bytes

__global__ __launch_bounds__(256) void fused_conv_kernel(const float* __restrict__ w1,
                                                         const float* __restrict__ b1,
                                                         const float* __restrict__ w2,
                                                         const float* __restrict__ b2,
                                                         const float* __restrict__ value)
{
    extern __shared__ unsigned dsm[];
    unsigned* sIn  = dsm;               // 4 ic-pairs x 728 (half2)
    unsigned* sMid = dsm + 4*PIN;       // 16 oc-pairs x 616 (half2)
    __shared__ float sB1[32];
    __shared__ float sB2[8];
    __shared__ float sVal[32];

    const int n  = blockIdx.z;
    const int X0 = blockIdx.x * FT_X;
    const int Y0 = blockIdx.y * FT_Y;
    const int tid  = threadIdx.x;
    const int lane = tid & 31, wid = tid >> 5;
    const int qr = lane >> 2, icb = lane & 3;

    if (tid < 32) {
        sB1[tid] = b1[tid];
        sVal[tid] = (X0 + tid < Pn) ? value[n*Pn + X0 + tid] : 0.f;
    }
    if (tid < 8)  sB2[tid] = b2[tid];

    // ---- stage input 20x36, 8ch packed as 4 half2 pairs ----
    for (int i = tid; i < IN_N; i += 256) {
        int r = i / IN_W, c = i - r*IN_W;
        int gy = Y0 - 2 + r, gx = X0 - 2 + c;
        bool ok = (gy >= 0 && gy < Pn && gx >= 0 && gx < Pn);
        const float* base = g_S + (size_t)(n*8)*PP2 + (size_t)gy*Pn + gx;
        #pragma unroll
        for (int j = 0; j < 4; j++) {
            float v0 = ok ? base[(size_t)(2*j)*PP2]   : 0.f;
            float v1 = ok ? base[(size_t)(2*j+1)*PP2] : 0.f;
            sIn[j*PIN + i] = packh2(v0, v1);
        }
    }

    // ---- conv1 weights: [pair p][ocg][2]: b0 @ shift 2p, b1 @ shift 2p+1 ----
    unsigned bw[5][4][2];
    #pragma unroll
    for (int p = 0; p < 5; p++) {
        int sA = 2*p, sB = 2*p + 1;
        #pragma unroll
        for (int g = 0; g < 4; g++) {
            int oc = g*8 + qr;
            bw[p][g][0] = packh2(w1[(oc*8 + 2*icb)*9 + sA],
                                 w1[(oc*8 + 2*icb + 1)*9 + sA]);
            bw[p][g][1] = (sB < 9) ? packh2(w1[(oc*8 + 2*icb)*9 + sB],
                                            w1[(oc*8 + 2*icb + 1)*9 + sB])
                                   : 0u;
        }
    }
    __syncthreads();

    // ---- phase 1: conv1 -> sMid (18x34 mid pixels, 39 M16 tiles) ----
    for (int t = wid; t < 39; t += 8) {
        int pr0 = t*16 + qr;
        int pr1 = pr0 + 8;
        int q0 = pr0 < MID_N ? pr0 : MID_N - 1;
        int q1 = pr1 < MID_N ? pr1 : MID_N - 1;
        int my0 = q0 / MID_W, mx0 = q0 - my0*MID_W;
        int my1 = q1 / MID_W, mx1 = q1 - my1*MID_W;
        int base0 = my0*IN_W + mx0;
        int base1 = my1*IN_W + mx1;
        float acc[4][4] = {};
        #pragma unroll
        for (int p = 0; p < 5; p++) {
            int sA = 2*p, sB = 2*p + 1;
            int offA = (sA/3)*IN_W + (sA - (sA/3)*3);
            int offB = (sB < 9) ? (sB/3)*IN_W + (sB - (sB/3)*3) : offA;
            unsigned a[4];
            a[0] = sIn[icb*PIN + base0 + offA];
            a[1] = sIn[icb*PIN + base1 + offA];
            a[2] = sIn[icb*PIN + base0 + offB];
            a[3] = sIn[icb*PIN + base1 + offB];
            #pragma unroll
            for (int g = 0; g < 4; g++) mma_f16_k16(acc[g], a, bw[p][g]);
        }
        bool s0 = pr0 < MID_N, s1 = pr1 < MID_N;
        int gy0 = Y0 - 1 + my0, gx0 = X0 - 1 + mx0;
        int gy1 = Y0 - 1 + my1, gx1 = X0 - 1 + mx1;
        bool in0 = (gy0 >= 0 && gy0 < Pn && gx0 >= 0 && gx0 < Pn);
        bool in1 = (gy1 >= 0 && gy1 < Pn && gx1 >= 0 && gx1 < Pn);
        #pragma unroll
        for (int g = 0; g < 4; g++) {
            int oc = g*8 + 2*icb;
            int pj = g*4 + icb;                   // oc-pair index
            if (s0) {
                float v0 = in0 ? fmaxf(acc[g][0] + sB1[oc],   0.f) : 0.f;
                float v1 = in0 ? fmaxf(acc[g][1] + sB1[oc+1], 0.f) : 0.f;
                sMid[pj*PMID + q0] = packh2(v0, v1);
            }
            if (s1) {
                float v2 = in1 ? fmaxf(acc[g][2] + sB1[oc],   0.f) : 0.f;
                float v3 = in1 ? fmaxf(acc[g][3] + sB1[oc+1], 0.f) : 0.f;
                sMid[pj*PMID + q1] = packh2(v2, v3);
            }
        }
    }
    __syncthreads();

    // ---- conv2 weights: [shift][kchunk][2], oc = qr ----
    unsigned bw2[9][2][2];
    #pragma unroll
    for (int s = 0; s < 9; s++)
        #pragma unroll
        for (int kc = 0; kc < 2; kc++) {
            bw2[s][kc][0] = packh2(w2[(qr*32 + 16*kc + 2*icb)*9 + s],
                                   w2[(qr*32 + 16*kc + 2*icb + 1)*9 + s]);
            bw2[s][kc][1] = packh2(w2[(qr*32 + 16*kc + 8 + 2*icb)*9 + s],
                                   w2[(qr*32 + 16*kc + 8 + 2*icb + 1)*9 + s]);
        }

    // ---- phase 2: conv2 + value reduction -> g_PART ----
    for (int t = wid; t < 32; t += 8) {
        int oy = t >> 1;
        int ox0 = (t & 1)*16 + qr, ox1 = ox0 + 8;
        float acc[4] = {};
        #pragma unroll
        for (int ky = 0; ky < 3; ky++) {
            #pragma unroll
            for (int kx = 0; kx < 3; kx++) {
                int r0 = (oy + ky)*MID_W + ox0 + kx;
                int r1 = (oy + ky)*MID_W + ox1 + kx;
                int s = ky*3 + kx;
                #pragma unroll
                for (int kc = 0; kc < 2; kc++) {
                    unsigned a[4];
                    a[0] = sMid[(8*kc + icb)*PMID     + r0];
                    a[1] = sMid[(8*kc + icb)*PMID     + r1];
                    a[2] = sMid[(8*kc + 4 + icb)*PMID + r0];
                    a[3] = sMid[(8*kc + 4 + icb)*PMID + r1];
                    mma_f16_k16(acc, a, bw2[s][kc]);
                }
            }
        }
        int oc = 2*icb;
        float bb0 = sB2[oc], bb1 = sB2[oc+1];
        float svA = sVal[ox0], svB = sVal[ox1];
        float r0 = fmaxf(acc[0] + bb0, 0.f);
        float r1 = fmaxf(acc[1] + bb1, 0.f);
        float r2 = fmaxf(acc[2] + bb0, 0.f);
        float r3 = fmaxf(acc[3] + bb1, 0.f);
        float s0 = r0*svA + r2*svB;
        float s1 = r1*svA + r3*svB;
        #pragma unroll
        for (int m = 4; m <= 16; m <<= 1) {
            s0 += __shfl_xor_sync(0xFFFFFFFFu, s0, m);
            s1 += __shfl_xor_sync(0xFFFFFFFFu, s1, m);
        }
        int y = Y0 + oy;
        if (qr == 0 && y < Pn) {
            int xp = blockIdx.x*2 + (t & 1);
            g_PART[((size_t)(n*Hn + oc    )*Pn + y)*64 + xp] = s0;
            g_PART[((size_t)(n*Hn + oc + 1)*Pn + y)*64 + xp] = s1;
        }
    }
}

// ============================================================
// K6: reduce partials -> out[b,p] = mean_h sum_xp
// ============================================================
__global__ __launch_bounds__(128) void reduce_kernel(float* __restrict__ out)
{
    const int bp = blockIdx.x;
    const int b = bp / Pn, p = bp % Pn;
    const int tid = threadIdx.x;
    float s = 0.f;
    for (int i = tid; i < 512; i += 128) {
        int h = i >> 6, xp = i & 63;
        if (xp < 58)
            s += g_PART[((size_t)(b*Hn + h)*Pn + p)*64 + xp];
    }
    __shared__ float red[128];
    red[tid] = s; __syncthreads();
    for (int st = 64; st > 0; st >>= 1) {
        if (tid < st) red[tid] += red[tid + st];
        __syncthreads();
    }
    if (tid == 0) out[bp] = red[0] * 0.125f;
}

// ============================================================
extern "C" void kernel_launch(void* const* d_in, const int* in_sizes, int n_in,
                              void* d_out, int out_size)
{
    const float* query = (const float*)d_in[0];
    const float* key_t = (const float*)d_in[1];
    const float* value = (const float*)d_in[2];
    const float* Wq    = (const float*)d_in[3];
    const float* bq    = (const float*)d_in[4];
    const float* Wk    = (const float*)d_in[5];
    const float* bk    = (const float*)d_in[6];
    const float* c1w   = (const float*)d_in[7];
    const float* c1b   = (const float*)d_in[8];
    const float* c2w   = (const float*)d_in[9];
    const float* c2b   = (const float*)d_in[10];
    float* out = (float*)d_out;

    static int smem_set = 0;
    if (!smem_set) {
        cudaFuncSetAttribute(fused_conv_kernel,
                             cudaFuncAttributeMaxDynamicSharedMemorySize, SMEM_FUSED);
        cudaFuncSetAttribute(scores_kernel,
                             cudaFuncAttributeMaxDynamicSharedMemorySize, SC_SMEM);
        smem_set = 1;
    }

    proj_kernel<<<dim3(8, 57), 256>>>(query, Wq, bq, 0);
    proj_kernel<<<dim3(8, 57), 256>>>(key_t, Wk, bk, 1);
    scores_kernel<<<dim3(15, 15, 32), 256, SC_SMEM>>>();
    modsm_kernel<<<dim3(113, 32), 256>>>();
    fused_conv_kernel<<<dim3(29, 57, 4), 256, SMEM_FUSED>>>(c1w, c1b, c2w, c2b, value);
    reduce_kernel<<<dim3(Bn*Pn), 128>>>(out);
}

// round 12
// speedup vs baseline: 3.3993x; 1.1350x over previous
#include <cuda_runtime.h>
#include <cuda_bf16.h>
#include <cuda_fp16.h>

#define Bn   4
#define Pn   900
#define Hn   8
#define DKn  64
#define DMn  512
#define PP2  (Pn*Pn)      // 810000
#define BHn  (Bn*Hn)      // 32

typedef unsigned long long u64_t;

// ---- fp16 m16n8k16 MMA ----
__device__ __forceinline__ void mma_f16_k16(float* c, const unsigned* a, const unsigned* b) {
    asm("mma.sync.aligned.m16n8k16.row.col.f32.f16.f16.f32 "
        "{%0,%1,%2,%3}, {%4,%5,%6,%7}, {%8,%9}, {%0,%1,%2,%3};"
        : "+f"(c[0]), "+f"(c[1]), "+f"(c[2]), "+f"(c[3])
        : "r"(a[0]), "r"(a[1]), "r"(a[2]), "r"(a[3]), "r"(b[0]), "r"(b[1]));
}
__device__ __forceinline__ unsigned packh2(float x, float y) {
    __half2 h = __floats2half2_rn(x, y);
    return *reinterpret_cast<unsigned*>(&h);
}
// split v into fp16 hi + fp16 lo (11+11 mantissa bits), packed pairs
__device__ __forceinline__ void split2(float v0, float v1, unsigned& hi, unsigned& lo) {
    __half h0 = __float2half_rn(v0), h1 = __float2half_rn(v1);
    float r0 = v0 - __half2float(h0), r1 = v1 - __half2float(h1);
    __half2 H = __halves2half2(h0, h1);
    hi = *reinterpret_cast<unsigned*>(&H);
    lo = packh2(r0, r1);
}

// order-preserving float->uint
__device__ __forceinline__ unsigned ord_f(float v) {
    unsigned b = __float_as_uint(v);
    return (b & 0x80000000u) ? ~b : (b | 0x80000000u);
}
__device__ __forceinline__ u64_t amax_key(float v, int p) {
    return ((u64_t)ord_f(v) << 32) | (u64_t)(0xFFFFFFFFu - (unsigned)p);
}

// ---- scratch (static device allocations; no runtime alloc) ----
__device__ float g_QP[Bn*Hn*Pn*DKn];        // [b,h,p,c]
__device__ float g_KP[Bn*Hn*Pn*DKn];        // [b,h,p,c]
__device__ float g_S [BHn*PP2];             // scores -> attn (conv input)
__device__ u64_t g_AMX[BHn*Pn];             // packed (value, ~p) argmax keys
__device__ float g_PART[Bn*Hn*Pn*64];       // conv2+einsum partials [b,h,p,xp]

// ============================================================
// K1: projection GEMM, fp16 3-MMA split precision (k16).
// out[b,h,p,c] = sum_k A[m,k]*W[n,k] + bias.  M=3600,N=512,K=512.
// K staged 32 fp32 = 16 half2-pairs/row, pad 20 (conflict-free).
// ============================================================
__global__ __launch_bounds__(256) void proj_kernel(const float* __restrict__ A,
                                                   const float* __restrict__ W,
                                                   const float* __restrict__ bias,
                                                   int which)
{
    __shared__ unsigned Ahi[64*20], Alo[64*20], Whi[64*20], Wlo[64*20];
    float* out = which ? g_KP : g_QP;
    const int bm = blockIdx.y * 64;
    const int bn = blockIdx.x * 64;
    const int tid = threadIdx.x;
    const int lane = tid & 31, wid = tid >> 5;
    const int qr = lane >> 2, icb = lane & 3;
    const int m0 = (wid & 3) * 16;
    const int n0 = (wid >> 2) * 32;
    float acc[4][4] = {};

    for (int k0 = 0; k0 < DMn; k0 += 32) {
        // 64 rows x 16 pairs for A and W each
        #pragma unroll
        for (int i = tid; i < 1024; i += 256) {
            int r = i >> 4, c2 = i & 15;
            int m = bm + r;
            int kc = k0 + 2*c2;
            float a0 = 0.f, a1 = 0.f;
            if (m < Bn*Pn) {
                a0 = A[(size_t)m*DMn + kc];
                a1 = A[(size_t)m*DMn + kc + 1];
            }
            float w0 = W[(size_t)(bn + r)*DMn + kc];
            float w1 = W[(size_t)(bn + r)*DMn + kc + 1];
            split2(a0, a1, Ahi[r*20 + c2], Alo[r*20 + c2]);
            split2(w0, w1, Whi[r*20 + c2], Wlo[r*20 + c2]);
        }
        __syncthreads();
        #pragma unroll
        for (int ks = 0; ks < 2; ks++) {
            int b8 = ks*8;                 // kpair base for this k16
            unsigned ah[4], al[4];
            int rA = (m0 + qr)*20 + b8 + icb;
            int rB = (m0 + qr + 8)*20 + b8 + icb;
            ah[0] = Ahi[rA];     ah[1] = Ahi[rB];
            ah[2] = Ahi[rA + 4]; ah[3] = Ahi[rB + 4];
            al[0] = Alo[rA];     al[1] = Alo[rB];
            al[2] = Alo[rA + 4]; al[3] = Alo[rB + 4];
            #pragma unroll
            for (int j = 0; j < 4; j++) {
                int rK = (n0 + j*8 + qr)*20 + b8 + icb;
                unsigned bh_[2] = { Whi[rK], Whi[rK + 4] };
                unsigned bl_[2] = { Wlo[rK], Wlo[rK + 4] };
                mma_f16_k16(acc[j], ah, bh_);
                mma_f16_k16(acc[j], ah, bl_);
                mma_f16_k16(acc[j], al, bh_);
            }
        }
        __syncthreads();
    }

    const int mA = bm + m0 + qr, mB = mA + 8;
    #pragma unroll
    for (int j = 0; j < 4; j++) {
        int na = bn + n0 + j*8 + 2*icb, nb2 = na + 1;
        if (mA < Bn*Pn) {
            int b = mA / Pn, p = mA % Pn;
            out[((b*Hn + (na  >> 6))*Pn + p)*DKn + (na  & 63)] = acc[j][0] + bias[na];
            out[((b*Hn + (nb2 >> 6))*Pn + p)*DKn + (nb2 & 63)] = acc[j][1] + bias[nb2];
        }
        if (mB < Bn*Pn) {
            int b = mB / Pn, p = mB % Pn;
            out[((b*Hn + (na  >> 6))*Pn + p)*DKn + (na  & 63)] = acc[j][2] + bias[na];
            out[((b*Hn + (nb2 >> 6))*Pn + p)*DKn + (nb2 & 63)] = acc[j][3] + bias[nb2];
        }
    }
}

// ============================================================
// K2: scores via fp16 3-MMA split (k16) + fused argmax.
// K=64 = 32 half2-pairs/row, pad 36 (conflict-free).
// ============================================================
__global__ __launch_bounds__(256) void scores_kernel()
{
    __shared__ unsigned Qhi[64*36], Qlo[64*36], Khi[64*36], Klo[64*36];

    const int bh = blockIdx.z;
    const float* Q = g_QP + bh*Pn*DKn;
    const float* K = g_KP + bh*Pn*DKn;
    const int p0 = blockIdx.y*64, q0 = blockIdx.x*64;
    const int tid = threadIdx.x;
    const int lane = tid & 31, wid = tid >> 5;
    const int qr = lane >> 2, icb = lane & 3;

    // stage + split: 64 rows x 32 kpairs for Q and K
    #pragma unroll
    for (int i = tid; i < 2048; i += 256) {
        int r = i >> 5, c2 = i & 31;
        int kc = 2*c2;
        float q0v = 0.f, q1v = 0.f, k0v = 0.f, k1v = 0.f;
        if (p0 + r < Pn) {
            q0v = Q[(p0+r)*DKn + kc];
            q1v = Q[(p0+r)*DKn + kc + 1];
        }
        if (q0 + r < Pn) {
            k0v = K[(q0+r)*DKn + kc];
            k1v = K[(q0+r)*DKn + kc + 1];
        }
        split2(q0v, q1v, Qhi[r*36 + c2], Qlo[r*36 + c2]);
        split2(k0v, k1v, Khi[r*36 + c2], Klo[r*36 + c2]);
    }
    __syncthreads();

    const int m0 = (wid & 3) * 16;
    const int n0 = (wid >> 2) * 32;
    float acc[4][4] = {};

    #pragma unroll
    for (int ks = 0; ks < 4; ks++) {
        int b8 = ks*8;                    // kpair base (k16 = 8 pairs)
        unsigned ah[4], al[4];
        int rA = (m0 + qr)*36 + b8 + icb;
        int rB = (m0 + qr + 8)*36 + b8 + icb;
        ah[0] = Qhi[rA];     ah[1] = Qhi[rB];
        ah[2] = Qhi[rA + 4]; ah[3] = Qhi[rB + 4];
        al[0] = Qlo[rA];     al[1] = Qlo[rB];
        al[2] = Qlo[rA + 4]; al[3] = Qlo[rB + 4];
        #pragma unroll
        for (int j = 0; j < 4; j++) {
            int rK = (n0 + j*8 + qr)*36 + b8 + icb;
            unsigned bh_[2] = { Khi[rK], Khi[rK + 4] };
            unsigned bl_[2] = { Klo[rK], Klo[rK + 4] };
            mma_f16_k16(acc[j], ah, bh_);
            mma_f16_k16(acc[j], ah, bl_);
            mma_f16_k16(acc[j], al, bh_);
        }
    }

    float* Sb = g_S + bh*PP2;
    const int pA = p0 + m0 + qr, pB = pA + 8;
    const bool vA = pA < Pn, vB = pB < Pn;
    #pragma unroll
    for (int j = 0; j < 4; j++) {
        int qa = q0 + n0 + j*8 + 2*icb;
        int qb = qa + 1;
        if (vA) {
            if (qa < Pn) Sb[pA*Pn + qa] = acc[j][0];
            if (qb < Pn) Sb[pA*Pn + qb] = acc[j][1];
        }
        if (vB) {
            if (qa < Pn) Sb[pB*Pn + qa] = acc[j][2];
            if (qb < Pn) Sb[pB*Pn + qb] = acc[j][3];
        }
        u64_t ka = 0, kb = 0;
        if (vA) { ka = amax_key(acc[j][0], pA); kb = amax_key(acc[j][1], pA); }
        if (vB) {
            u64_t t = amax_key(acc[j][2], pB); if (t > ka) ka = t;
            t = amax_key(acc[j][3], pB);       if (t > kb) kb = t;
        }
        #pragma unroll
        for (int m = 4; m <= 16; m <<= 1) {
            u64_t ta = __shfl_xor_sync(0xFFFFFFFFu, ka, m);
            u64_t tb = __shfl_xor_sync(0xFFFFFFFFu, kb, m);
            if (ta > ka) ka = ta;
            if (tb > kb) kb = tb;
        }
        if (qr == 0) {
            if (qa < Pn) atomicMax(&g_AMX[bh*Pn + qa], ka);
            if (qb < Pn) atomicMax(&g_AMX[bh*Pn + qb], kb);
        }
    }
}

// ============================================================
// K4: gaussian (separable table) + scale + softmax; warp-per-row.
// ============================================================
__global__ __launch_bounds__(256) void modsm_kernel()
{
    __shared__ float sT[900];
    __shared__ unsigned char sFX[900], sFY[900];
    const int bh = blockIdx.y;
    const int p0 = blockIdx.x * 8;
    const int tid = threadIdx.x, lane = tid & 31, wrp = tid >> 5;

    for (int i = tid; i < 900; i += 256) {
        int a = i / 30, bc = i - (i/30)*30;
        float d = (-1.f + (2.f/29.f)*(float)a) - (float)bc;
        sT[i] = __expf(-d*d*0.02f);
        unsigned id = 0xFFFFFFFFu - (unsigned)(g_AMX[bh*Pn + i] & 0xFFFFFFFFu);
        sFX[i] = (unsigned char)(id % 30);
        sFY[i] = (unsigned char)(id / 30);
    }
    __syncthreads();

    const int p = p0 + wrp;
    if (p >= Pn) return;
    float* Srow = g_S + (size_t)bh*PP2 + (size_t)p*Pn;
    const float* Tx = sT + (p % 30)*30;
    const float* Ty = sT + (p / 30)*30;

    float v[29];
    float lmax = -1e30f;
    #pragma unroll
    for (int i = 0; i < 29; i++) {
        int q = lane + i*32;
        if (q < Pn) {
            float g = Tx[sFX[q]] * Ty[sFY[q]];
            v[i] = g * Srow[q] * 0.125f;
            lmax = fmaxf(lmax, v[i]);
        } else v[i] = -1e30f;
    }
    #pragma unroll
    for (int m = 16; m > 0; m >>= 1)
        lmax = fmaxf(lmax, __shfl_xor_sync(0xFFFFFFFFu, lmax, m));

    float lsum = 0.f;
    #pragma unroll
    for (int i = 0; i < 29; i++) {
        float e = __expf(v[i] - lmax);
        v[i] = e;
        if (lane + i*32 < Pn) lsum += e;
    }
    #pragma unroll
    for (int m = 16; m > 0; m >>= 1)
        lsum += __shfl_xor_sync(0xFFFFFFFFu, lsum, m);
    const float inv = 1.f / lsum;
    #pragma unroll
    for (int i = 0; i < 29; i++) {
        int q = lane + i*32;
        if (q < Pn) Srow[q] = v[i] * inv;
    }
}

// ============================================================
// K5: FUSED conv1+conv2+value-einsum, fp16 m16n8k16 MMA.
// ============================================================
#define FT_Y   16
#define FT_X   32
#define MID_W  34
#define MID_N  612
#define IN_W   36
#define IN_N   720
#define PIN    728
#define PMID   616
#define SMEM_FUSED ((4*PIN + 16*PMID)*4)   // 51136 bytes

__global__ __launch_bounds__(256) void fused_conv_kernel(const float* __restrict__ w1,
                                                         const float* __restrict__ b1,
                                                         const float* __restrict__ w2,
                                                         const float* __restrict__ b2,
                                                         const float* __restrict__ value)
{
    extern __shared__ unsigned dsm[];
    unsigned* sIn  = dsm;               // 4 ic-pairs x 728 (half2)
    unsigned* sMid = dsm + 4*PIN;       // 16 oc-pairs x 616 (half2)
    __shared__ float sB1[32];
    __shared__ float sB2[8];
    __shared__ float sVal[32];

    const int n  = blockIdx.z;
    const int X0 = blockIdx.x * FT_X;
    const int Y0 = blockIdx.y * FT_Y;
    const int tid  = threadIdx.x;
    const int lane = tid & 31, wid = tid >> 5;
    const int qr = lane >> 2, icb = lane & 3;

    if (tid < 32) {
        sB1[tid] = b1[tid];
        sVal[tid] = (X0 + tid < Pn) ? value[n*Pn + X0 + tid] : 0.f;
    }
    if (tid < 8)  sB2[tid] = b2[tid];

    for (int i = tid; i < IN_N; i += 256) {
        int r = i / IN_W, c = i - r*IN_W;
        int gy = Y0 - 2 + r, gx = X0 - 2 + c;
        bool ok = (gy >= 0 && gy < Pn && gx >= 0 && gx < Pn);
        const float* base = g_S + (size_t)(n*8)*PP2 + (size_t)gy*Pn + gx;
        #pragma unroll
        for (int j = 0; j < 4; j++) {
            float v0 = ok ? base[(size_t)(2*j)*PP2]   : 0.f;
            float v1 = ok ? base[(size_t)(2*j+1)*PP2] : 0.f;
            sIn[j*PIN + i] = packh2(v0, v1);
        }
    }

    unsigned bw[5][4][2];
    #pragma unroll
    for (int p = 0; p < 5; p++) {
        int sA = 2*p, sB = 2*p + 1;
        #pragma unroll
        for (int g = 0; g < 4; g++) {
            int oc = g*8 + qr;
            bw[p][g][0] = packh2(w1[(oc*8 + 2*icb)*9 + sA],
                                 w1[(oc*8 + 2*icb + 1)*9 + sA]);
            bw[p][g][1] = (sB < 9) ? packh2(w1[(oc*8 + 2*icb)*9 + sB],
                                            w1[(oc*8 + 2*icb + 1)*9 + sB])
                                   : 0u;
        }
    }
    __syncthreads();

    for (int t = wid; t < 39; t += 8) {
        int pr0 = t*16 + qr;
        int pr1 = pr0 + 8;
        int q0 = pr0 < MID_N ? pr0 : MID_N - 1;
        int q1 = pr1 < MID_N ? pr1 : MID_N - 1;
        int my0 = q0 / MID_W, mx0 = q0 - my0*MID_W;
        int my1 = q1 / MID_W, mx1 = q1 - my1*MID_W;
        int base0 = my0*IN_W + mx0;
        int base1 = my1*IN_W + mx1;
        float acc[4][4] = {};
        #pragma unroll
        for (int p = 0; p < 5; p++) {
            int sA = 2*p, sB = 2*p + 1;
            int offA = (sA/3)*IN_W + (sA - (sA/3)*3);
            int offB = (sB < 9) ? (sB/3)*IN_W + (sB - (sB/3)*3) : offA;
            unsigned a[4];
            a[0] = sIn[icb*PIN + base0 + offA];
            a[1] = sIn[icb*PIN + base1 + offA];
            a[2] = sIn[icb*PIN + base0 + offB];
            a[3] = sIn[icb*PIN + base1 + offB];
            #pragma unroll
            for (int g = 0; g < 4; g++) mma_f16_k16(acc[g], a, bw[p][g]);
        }
        bool s0 = pr0 < MID_N, s1 = pr1 < MID_N;
        int gy0 = Y0 - 1 + my0, gx0 = X0 - 1 + mx0;
        int gy1 = Y0 - 1 + my1, gx1 = X0 - 1 + mx1;
        bool in0 = (gy0 >= 0 && gy0 < Pn && gx0 >= 0 && gx0 < Pn);
        bool in1 = (gy1 >= 0 && gy1 < Pn && gx1 >= 0 && gx1 < Pn);
        #pragma unroll
        for (int g = 0; g < 4; g++) {
            int oc = g*8 + 2*icb;
            int pj = g*4 + icb;
            if (s0) {
                float v0 = in0 ? fmaxf(acc[g][0] + sB1[oc],   0.f) : 0.f;
                float v1 = in0 ? fmaxf(acc[g][1] + sB1[oc+1], 0.f) : 0.f;
                sMid[pj*PMID + q0] = packh2(v0, v1);
            }
            if (s1) {
                float v2 = in1 ? fmaxf(acc[g][2] + sB1[oc],   0.f) : 0.f;
                float v3 = in1 ? fmaxf(acc[g][3] + sB1[oc+1], 0.f) : 0.f;
                sMid[pj*PMID + q1] = packh2(v2, v3);
            }
        }
    }
    __syncthreads();

    unsigned bw2[9][2][2];
    #pragma unroll
    for (int s = 0; s < 9; s++)
        #pragma unroll
        for (int kc = 0; kc < 2; kc++) {
            bw2[s][kc][0] = packh2(w2[(qr*32 + 16*kc + 2*icb)*9 + s],
                                   w2[(qr*32 + 16*kc + 2*icb + 1)*9 + s]);
            bw2[s][kc][1] = packh2(w2[(qr*32 + 16*kc + 8 + 2*icb)*9 + s],
                                   w2[(qr*32 + 16*kc + 8 + 2*icb + 1)*9 + s]);
        }

    for (int t = wid; t < 32; t += 8) {
        int oy = t >> 1;
        int ox0 = (t & 1)*16 + qr, ox1 = ox0 + 8;
        float acc[4] = {};
        #pragma unroll
        for (int ky = 0; ky < 3; ky++) {
            #pragma unroll
            for (int kx = 0; kx < 3; kx++) {
                int r0 = (oy + ky)*MID_W + ox0 + kx;
                int r1 = (oy + ky)*MID_W + ox1 + kx;
                int s = ky*3 + kx;
                #pragma unroll
                for (int kc = 0; kc < 2; kc++) {
                    unsigned a[4];
                    a[0] = sMid[(8*kc + icb)*PMID     + r0];
                    a[1] = sMid[(8*kc + icb)*PMID     + r1];
                    a[2] = sMid[(8*kc + 4 + icb)*PMID + r0];
                    a[3] = sMid[(8*kc + 4 + icb)*PMID + r1];
                    mma_f16_k16(acc, a, bw2[s][kc]);
                }
            }
        }
        int oc = 2*icb;
        float bb0 = sB2[oc], bb1 = sB2[oc+1];
        float svA = sVal[ox0], svB = sVal[ox1];
        float r0 = fmaxf(acc[0] + bb0, 0.f);
        float r1 = fmaxf(acc[1] + bb1, 0.f);
        float r2 = fmaxf(acc[2] + bb0, 0.f);
        float r3 = fmaxf(acc[3] + bb1, 0.f);
        float s0 = r0*svA + r2*svB;
        float s1 = r1*svA + r3*svB;
        #pragma unroll
        for (int m = 4; m <= 16; m <<= 1) {
            s0 += __shfl_xor_sync(0xFFFFFFFFu, s0, m);
            s1 += __shfl_xor_sync(0xFFFFFFFFu, s1, m);
        }
        int y = Y0 + oy;
        if (qr == 0 && y < Pn) {
            int xp = blockIdx.x*2 + (t & 1);
            g_PART[((size_t)(n*Hn + oc    )*Pn + y)*64 + xp] = s0;
            g_PART[((size_t)(n*Hn + oc + 1)*Pn + y)*64 + xp] = s1;
        }
    }
}

// ============================================================
// K6: reduce partials -> out[b,p] = mean_h sum_xp
// ============================================================
__global__ __launch_bounds__(128) void reduce_kernel(float* __restrict__ out)
{
    const int bp = blockIdx.x;
    const int b = bp / Pn, p = bp % Pn;
    const int tid = threadIdx.x;
    float s = 0.f;
    for (int i = tid; i < 512; i += 128) {
        int h = i >> 6, xp = i & 63;
        if (xp < 58)
            s += g_PART[((size_t)(b*Hn + h)*Pn + p)*64 + xp];
    }
    __shared__ float red[128];
    red[tid] = s; __syncthreads();
    for (int st = 64; st > 0; st >>= 1) {
        if (tid < st) red[tid] += red[tid + st];
        __syncthreads();
    }
    if (tid == 0) out[bp] = red[0] * 0.125f;
}

// ============================================================
extern "C" void kernel_launch(void* const* d_in, const int* in_sizes, int n_in,
                              void* d_out, int out_size)
{
    const float* query = (const float*)d_in[0];
    const float* key_t = (const float*)d_in[1];
    const float* value = (const float*)d_in[2];
    const float* Wq    = (const float*)d_in[3];
    const float* bq    = (const float*)d_in[4];
    const float* Wk    = (const float*)d_in[5];
    const float* bk    = (const float*)d_in[6];
    const float* c1w   = (const float*)d_in[7];
    const float* c1b   = (const float*)d_in[8];
    const float* c2w   = (const float*)d_in[9];
    const float* c2b   = (const float*)d_in[10];
    float* out = (float*)d_out;

    static int smem_set = 0;
    if (!smem_set) {
        cudaFuncSetAttribute(fused_conv_kernel,
                             cudaFuncAttributeMaxDynamicSharedMemorySize, SMEM_FUSED);
        smem_set = 1;
    }

    proj_kernel<<<dim3(8, 57), 256>>>(query, Wq, bq, 0);
    proj_kernel<<<dim3(8, 57), 256>>>(key_t, Wk, bk, 1);
    scores_kernel<<<dim3(15, 15, 32), 256>>>();
    modsm_kernel<<<dim3(113, 32), 256>>>();
    fused_conv_kernel<<<dim3(29, 57, 4), 256, SMEM_FUSED>>>(c1w, c1b, c2w, c2b, value);
    reduce_kernel<<<dim3(Bn*Pn), 128>>>(out);
}

// round 13
// speedup vs baseline: 3.4296x; 1.0089x over previous
#include <cuda_runtime.h>
#include <cuda_bf16.h>
#include <cuda_fp16.h>

#define Bn   4
#define Pn   900
#define Hn   8
#define DKn  64
#define DMn  512
#define PP2  (Pn*Pn)      // 810000
#define BHn  (Bn*Hn)      // 32

typedef unsigned long long u64_t;

// ---- fp16 m16n8k16 MMA ----
__device__ __forceinline__ void mma_f16_k16(float* c, const unsigned* a, const unsigned* b) {
    asm("mma.sync.aligned.m16n8k16.row.col.f32.f16.f16.f32 "
        "{%0,%1,%2,%3}, {%4,%5,%6,%7}, {%8,%9}, {%0,%1,%2,%3};"
        : "+f"(c[0]), "+f"(c[1]), "+f"(c[2]), "+f"(c[3])
        : "r"(a[0]), "r"(a[1]), "r"(a[2]), "r"(a[3]), "r"(b[0]), "r"(b[1]));
}
__device__ __forceinline__ unsigned packh2(float x, float y) {
    __half2 h = __floats2half2_rn(x, y);
    return *reinterpret_cast<unsigned*>(&h);
}
// split (v0,v1) into fp16 hi pair + fp16 lo pair (11+11 mantissa bits)
__device__ __forceinline__ void split2(float v0, float v1, unsigned& hi, unsigned& lo) {
    __half h0 = __float2half_rn(v0), h1 = __float2half_rn(v1);
    float r0 = v0 - __half2float(h0), r1 = v1 - __half2float(h1);
    __half2 H = __halves2half2(h0, h1);
    hi = *reinterpret_cast<unsigned*>(&H);
    lo = packh2(r0, r1);
}

// order-preserving float->uint
__device__ __forceinline__ unsigned ord_f(float v) {
    unsigned b = __float_as_uint(v);
    return (b & 0x80000000u) ? ~b : (b | 0x80000000u);
}
__device__ __forceinline__ u64_t amax_key(float v, int p) {
    return ((u64_t)ord_f(v) << 32) | (u64_t)(0xFFFFFFFFu - (unsigned)p);
}

// ---- scratch (static device allocations; no runtime alloc) ----
__device__ unsigned g_Qh[BHn*Pn*32];        // Q hi pairs [bh][p][c2]
__device__ unsigned g_Ql[BHn*Pn*32];        // Q lo pairs
__device__ unsigned g_Kh[BHn*Pn*32];        // K hi pairs
__device__ unsigned g_Kl[BHn*Pn*32];        // K lo pairs
__device__ float    g_S [BHn*PP2];          // fp32 scores (softmax input)
__device__ u64_t    g_AMX[BHn*Pn];          // packed (value, ~p) argmax keys
__device__ unsigned g_ATT[Bn*4*PP2];        // attn half2 ch-pairs [b][j][pos]
__device__ float    g_PART[Bn*Hn*Pn*64];    // conv2+einsum partials

// ============================================================
// K1: projection GEMM (both Q and K via blockIdx.z), fp16 3-MMA split.
// Epilogue writes pre-split half2 hi/lo pairs (consumed by scores).
// ============================================================
__global__ __launch_bounds__(256) void proj_kernel(const float* __restrict__ query,
                                                   const float* __restrict__ key_t,
                                                   const float* __restrict__ Wq,
                                                   const float* __restrict__ bq,
                                                   const float* __restrict__ Wk,
                                                   const float* __restrict__ bk)
{
    __shared__ unsigned Ahi[64*20], Alo[64*20], Whi[64*20], Wlo[64*20];
    const int z = blockIdx.z;
    const float* A    = z ? key_t : query;
    const float* W    = z ? Wk : Wq;
    const float* bias = z ? bk : bq;
    unsigned* outh = z ? g_Kh : g_Qh;
    unsigned* outl = z ? g_Kl : g_Ql;

    const int bm = blockIdx.y * 64;
    const int bn = blockIdx.x * 64;
    const int tid = threadIdx.x;
    const int lane = tid & 31, wid = tid >> 5;
    const int qr = lane >> 2, icb = lane & 3;
    const int m0 = (wid & 3) * 16;
    const int n0 = (wid >> 2) * 32;
    float acc[4][4] = {};

    for (int k0 = 0; k0 < DMn; k0 += 32) {
        #pragma unroll
        for (int i = tid; i < 1024; i += 256) {
            int r = i >> 4, c2 = i & 15;
            int m = bm + r;
            int kc = k0 + 2*c2;
            float a0 = 0.f, a1 = 0.f;
            if (m < Bn*Pn) {
                a0 = A[(size_t)m*DMn + kc];
                a1 = A[(size_t)m*DMn + kc + 1];
            }
            float w0 = W[(size_t)(bn + r)*DMn + kc];
            float w1 = W[(size_t)(bn + r)*DMn + kc + 1];
            split2(a0, a1, Ahi[r*20 + c2], Alo[r*20 + c2]);
            split2(w0, w1, Whi[r*20 + c2], Wlo[r*20 + c2]);
        }
        __syncthreads();
        #pragma unroll
        for (int ks = 0; ks < 2; ks++) {
            int b8 = ks*8;
            unsigned ah[4], al[4];
            int rA = (m0 + qr)*20 + b8 + icb;
            int rB = (m0 + qr + 8)*20 + b8 + icb;
            ah[0] = Ahi[rA];     ah[1] = Ahi[rB];
            ah[2] = Ahi[rA + 4]; ah[3] = Ahi[rB + 4];
            al[0] = Alo[rA];     al[1] = Alo[rB];
            al[2] = Alo[rA + 4]; al[3] = Alo[rB + 4];
            #pragma unroll
            for (int j = 0; j < 4; j++) {
                int rK = (n0 + j*8 + qr)*20 + b8 + icb;
                unsigned bh_[2] = { Whi[rK], Whi[rK + 4] };
                unsigned bl_[2] = { Wlo[rK], Wlo[rK + 4] };
                mma_f16_k16(acc[j], ah, bh_);
                mma_f16_k16(acc[j], ah, bl_);
                mma_f16_k16(acc[j], al, bh_);
            }
        }
        __syncthreads();
    }

    const int mA = bm + m0 + qr, mB = mA + 8;
    #pragma unroll
    for (int j = 0; j < 4; j++) {
        int na = bn + n0 + j*8 + 2*icb;       // even; pair stays within head
        int h = na >> 6, c2 = (na & 63) >> 1;
        if (mA < Bn*Pn) {
            int b = mA / Pn, p = mA % Pn;
            unsigned hi, lo;
            split2(acc[j][0] + bias[na], acc[j][1] + bias[na+1], hi, lo);
            size_t idx = ((size_t)(b*Hn + h)*Pn + p)*32 + c2;
            outh[idx] = hi; outl[idx] = lo;
        }
        if (mB < Bn*Pn) {
            int b = mB / Pn, p = mB % Pn;
            unsigned hi, lo;
            split2(acc[j][2] + bias[na], acc[j][3] + bias[na+1], hi, lo);
            size_t idx = ((size_t)(b*Hn + h)*Pn + p)*32 + c2;
            outh[idx] = hi; outl[idx] = lo;
        }
    }
}

// ============================================================
// K2: scores via fp16 3-MMA split (k16) + fused argmax.
// Staging = pure u32 copies of pre-split operands.
// ============================================================
__global__ __launch_bounds__(256) void scores_kernel()
{
    __shared__ unsigned Qhi[64*36], Qlo[64*36], Khi[64*36], Klo[64*36];

    const int bh = blockIdx.z;
    const int p0 = blockIdx.y*64, q0 = blockIdx.x*64;
    const int tid = threadIdx.x;
    const int lane = tid & 31, wid = tid >> 5;
    const int qr = lane >> 2, icb = lane & 3;

    #pragma unroll
    for (int i = tid; i < 2048; i += 256) {
        int r = i >> 5, c2 = i & 31;
        unsigned qh = 0, ql = 0, kh = 0, kl = 0;
        if (p0 + r < Pn) {
            size_t idx = ((size_t)bh*Pn + p0 + r)*32 + c2;
            qh = g_Qh[idx]; ql = g_Ql[idx];
        }
        if (q0 + r < Pn) {
            size_t idx = ((size_t)bh*Pn + q0 + r)*32 + c2;
            kh = g_Kh[idx]; kl = g_Kl[idx];
        }
        Qhi[r*36 + c2] = qh; Qlo[r*36 + c2] = ql;
        Khi[r*36 + c2] = kh; Klo[r*36 + c2] = kl;
    }
    __syncthreads();

    const int m0 = (wid & 3) * 16;
    const int n0 = (wid >> 2) * 32;
    float acc[4][4] = {};

    #pragma unroll
    for (int ks = 0; ks < 4; ks++) {
        int b8 = ks*8;
        unsigned ah[4], al[4];
        int rA = (m0 + qr)*36 + b8 + icb;
        int rB = (m0 + qr + 8)*36 + b8 + icb;
        ah[0] = Qhi[rA];     ah[1] = Qhi[rB];
        ah[2] = Qhi[rA + 4]; ah[3] = Qhi[rB + 4];
        al[0] = Qlo[rA];     al[1] = Qlo[rB];
        al[2] = Qlo[rA + 4]; al[3] = Qlo[rB + 4];
        #pragma unroll
        for (int j = 0; j < 4; j++) {
            int rK = (n0 + j*8 + qr)*36 + b8 + icb;
            unsigned bh_[2] = { Khi[rK], Khi[rK + 4] };
            unsigned bl_[2] = { Klo[rK], Klo[rK + 4] };
            mma_f16_k16(acc[j], ah, bh_);
            mma_f16_k16(acc[j], ah, bl_);
            mma_f16_k16(acc[j], al, bh_);
        }
    }

    float* Sb = g_S + (size_t)bh*PP2;
    const int pA = p0 + m0 + qr, pB = pA + 8;
    const bool vA = pA < Pn, vB = pB < Pn;
    #pragma unroll
    for (int j = 0; j < 4; j++) {
        int qa = q0 + n0 + j*8 + 2*icb;
        int qb = qa + 1;
        if (vA) {
            if (qa < Pn) Sb[pA*Pn + qa] = acc[j][0];
            if (qb < Pn) Sb[pA*Pn + qb] = acc[j][1];
        }
        if (vB) {
            if (qa < Pn) Sb[pB*Pn + qa] = acc[j][2];
            if (qb < Pn) Sb[pB*Pn + qb] = acc[j][3];
        }
        u64_t ka = 0, kb = 0;
        if (vA) { ka = amax_key(acc[j][0], pA); kb = amax_key(acc[j][1], pA); }
        if (vB) {
            u64_t t = amax_key(acc[j][2], pB); if (t > ka) ka = t;
            t = amax_key(acc[j][3], pB);       if (t > kb) kb = t;
        }
        #pragma unroll
        for (int m = 4; m <= 16; m <<= 1) {
            u64_t ta = __shfl_xor_sync(0xFFFFFFFFu, ka, m);
            u64_t tb = __shfl_xor_sync(0xFFFFFFFFu, kb, m);
            if (ta > ka) ka = ta;
            if (tb > kb) kb = tb;
        }
        if (qr == 0) {
            if (qa < Pn) atomicMax(&g_AMX[bh*Pn + qa], ka);
            if (qb < Pn) atomicMax(&g_AMX[bh*Pn + qb], kb);
        }
    }
}

// ============================================================
// K4: gaussian + scale + softmax; warp = one p-row of a CHANNEL PAIR.
// Emits conv-ready packed half2 attn into g_ATT[b][j][pos].
// ============================================================
__global__ __launch_bounds__(256) void modsm_kernel()
{
    __shared__ float sT[900];
    __shared__ unsigned char sFX0[900], sFY0[900], sFX1[900], sFY1[900];
    const int bj = blockIdx.y;               // b*4 + j
    const int b = bj >> 2, j = bj & 3;
    const int bh0 = b*Hn + 2*j, bh1 = bh0 + 1;
    const int p0 = blockIdx.x * 8;
    const int tid = threadIdx.x, lane = tid & 31, wrp = tid >> 5;

    for (int i = tid; i < 900; i += 256) {
        int a = i / 30, bc = i - (i/30)*30;
        float d = (-1.f + (2.f/29.f)*(float)a) - (float)bc;
        sT[i] = __expf(-d*d*0.02f);
        unsigned id0 = 0xFFFFFFFFu - (unsigned)(g_AMX[bh0*Pn + i] & 0xFFFFFFFFu);
        unsigned id1 = 0xFFFFFFFFu - (unsigned)(g_AMX[bh1*Pn + i] & 0xFFFFFFFFu);
        sFX0[i] = (unsigned char)(id0 % 30); sFY0[i] = (unsigned char)(id0 / 30);
        sFX1[i] = (unsigned char)(id1 % 30); sFY1[i] = (unsigned char)(id1 / 30);
    }
    __syncthreads();

    const int p = p0 + wrp;
    if (p >= Pn) return;
    const float* S0 = g_S + (size_t)bh0*PP2 + (size_t)p*Pn;
    const float* S1 = g_S + (size_t)bh1*PP2 + (size_t)p*Pn;
    const float* Tx = sT + (p % 30)*30;
    const float* Ty = sT + (p / 30)*30;

    float v0[29], v1[29];
    float m0 = -1e30f, m1 = -1e30f;
    #pragma unroll
    for (int i = 0; i < 29; i++) {
        int q = lane + i*32;
        if (q < Pn) {
            float s0 = S0[q], s1 = S1[q];
            float g0 = Tx[sFX0[q]] * Ty[sFY0[q]];
            float g1 = Tx[sFX1[q]] * Ty[sFY1[q]];
            v0[i] = g0 * s0 * 0.125f;
            v1[i] = g1 * s1 * 0.125f;
            m0 = fmaxf(m0, v0[i]);
            m1 = fmaxf(m1, v1[i]);
        } else { v0[i] = -1e30f; v1[i] = -1e30f; }
    }
    #pragma unroll
    for (int m = 16; m > 0; m >>= 1) {
        m0 = fmaxf(m0, __shfl_xor_sync(0xFFFFFFFFu, m0, m));
        m1 = fmaxf(m1, __shfl_xor_sync(0xFFFFFFFFu, m1, m));
    }

    float sum0 = 0.f, sum1 = 0.f;
    #pragma unroll
    for (int i = 0; i < 29; i++) {
        float e0 = __expf(v0[i] - m0);
        float e1 = __expf(v1[i] - m1);
        v0[i] = e0; v1[i] = e1;
        if (lane + i*32 < Pn) { sum0 += e0; sum1 += e1; }
    }
    #pragma unroll
    for (int m = 16; m > 0; m >>= 1) {
        sum0 += __shfl_xor_sync(0xFFFFFFFFu, sum0, m);
        sum1 += __shfl_xor_sync(0xFFFFFFFFu, sum1, m);
    }
    const float inv0 = 1.f / sum0, inv1 = 1.f / sum1;
    unsigned* dst = g_ATT + (size_t)bj*PP2 + (size_t)p*Pn;
    #pragma unroll
    for (int i = 0; i < 29; i++) {
        int q = lane + i*32;
        if (q < Pn) dst[q] = packh2(v0[i]*inv0, v1[i]*inv1);
    }
}

// ============================================================
// K5: FUSED conv1+conv2+value-einsum, fp16 m16n8k16 MMA.
// Input already packed half2 ch-pairs in g_ATT -> staging = u32 copies.
// ============================================================
#define FT_Y   16
#define FT_X   32
#define MID_W  34
#define MID_N  612
#define IN_W   36
#define IN_N   720
#define PIN    728
#define PMID   616
#define SMEM_FUSED ((4*PIN + 16*PMID)*4)   // 51136 bytes

__global__ __launch_bounds__(256) void fused_conv_kernel(const float* __restrict__ w1,
                                                         const float* __restrict__ b1,
                                                         const float* __restrict__ w2,
                                                         const float* __restrict__ b2,
                                                         const float* __restrict__ value)
{
    extern __shared__ unsigned dsm[];
    unsigned* sIn  = dsm;               // 4 ic-pairs x 728 (half2)
    unsigned* sMid = dsm + 4*PIN;       // 16 oc-pairs x 616 (half2)
    __shared__ float sB1[32];
    __shared__ float sB2[8];
    __shared__ float sVal[32];

    const int n  = blockIdx.z;
    const int X0 = blockIdx.x * FT_X;
    const int Y0 = blockIdx.y * FT_Y;
    const int tid  = threadIdx.x;
    const int lane = tid & 31, wid = tid >> 5;
    const int qr = lane >> 2, icb = lane & 3;

    if (tid < 32) {
        sB1[tid] = b1[tid];
        sVal[tid] = (X0 + tid < Pn) ? value[n*Pn + X0 + tid] : 0.f;
    }
    if (tid < 8)  sB2[tid] = b2[tid];

    for (int i = tid; i < IN_N; i += 256) {
        int r = i / IN_W, c = i - r*IN_W;
        int gy = Y0 - 2 + r, gx = X0 - 2 + c;
        bool ok = (gy >= 0 && gy < Pn && gx >= 0 && gx < Pn);
        size_t base = (size_t)gy*Pn + gx;
        #pragma unroll
        for (int j = 0; j < 4; j++)
            sIn[j*PIN + i] = ok ? g_ATT[(size_t)(n*4 + j)*PP2 + base] : 0u;
    }

    unsigned bw[5][4][2];
    #pragma unroll
    for (int p = 0; p < 5; p++) {
        int sA = 2*p, sB = 2*p + 1;
        #pragma unroll
        for (int g = 0; g < 4; g++) {
            int oc = g*8 + qr;
            bw[p][g][0] = packh2(w1[(oc*8 + 2*icb)*9 + sA],
                                 w1[(oc*8 + 2*icb + 1)*9 + sA]);
            bw[p][g][1] = (sB < 9) ? packh2(w1[(oc*8 + 2*icb)*9 + sB],
                                            w1[(oc*8 + 2*icb + 1)*9 + sB])
                                   : 0u;
        }
    }
    __syncthreads();

    for (int t = wid; t < 39; t += 8) {
        int pr0 = t*16 + qr;
        int pr1 = pr0 + 8;
        int q0 = pr0 < MID_N ? pr0 : MID_N - 1;
        int q1 = pr1 < MID_N ? pr1 : MID_N - 1;
        int my0 = q0 / MID_W, mx0 = q0 - my0*MID_W;
        int my1 = q1 / MID_W, mx1 = q1 - my1*MID_W;
        int base0 = my0*IN_W + mx0;
        int base1 = my1*IN_W + mx1;
        float acc[4][4] = {};
        #pragma unroll
        for (int p = 0; p < 5; p++) {
            int sA = 2*p, sB = 2*p + 1;
            int offA = (sA/3)*IN_W + (sA - (sA/3)*3);
            int offB = (sB < 9) ? (sB/3)*IN_W + (sB - (sB/3)*3) : offA;
            unsigned a[4];
            a[0] = sIn[icb*PIN + base0 + offA];
            a[1] = sIn[icb*PIN + base1 + offA];
            a[2] = sIn[icb*PIN + base0 + offB];
            a[3] = sIn[icb*PIN + base1 + offB];
            #pragma unroll
            for (int g = 0; g < 4; g++) mma_f16_k16(acc[g], a, bw[p][g]);
        }
        bool s0 = pr0 < MID_N, s1 = pr1 < MID_N;
        int gy0 = Y0 - 1 + my0, gx0 = X0 - 1 + mx0;
        int gy1 = Y0 - 1 + my1, gx1 = X0 - 1 + mx1;
        bool in0 = (gy0 >= 0 && gy0 < Pn && gx0 >= 0 && gx0 < Pn);
        bool in1 = (gy1 >= 0 && gy1 < Pn && gx1 >= 0 && gx1 < Pn);
        #pragma unroll
        for (int g = 0; g < 4; g++) {
            int oc = g*8 + 2*icb;
            int pj = g*4 + icb;
            if (s0) {
                float v0 = in0 ? fmaxf(acc[g][0] + sB1[oc],   0.f) : 0.f;
                float v1 = in0 ? fmaxf(acc[g][1] + sB1[oc+1], 0.f) : 0.f;
                sMid[pj*PMID + q0] = packh2(v0, v1);
            }
            if (s1) {
                float v2 = in1 ? fmaxf(acc[g][2] + sB1[oc],   0.f) : 0.f;
                float v3 = in1 ? fmaxf(acc[g][3] + sB1[oc+1], 0.f) : 0.f;
                sMid[pj*PMID + q1] = packh2(v2, v3);
            }
        }
    }
    __syncthreads();

    unsigned bw2[9][2][2];
    #pragma unroll
    for (int s = 0; s < 9; s++)
        #pragma unroll
        for (int kc = 0; kc < 2; kc++) {
            bw2[s][kc][0] = packh2(w2[(qr*32 + 16*kc + 2*icb)*9 + s],
                                   w2[(qr*32 + 16*kc + 2*icb + 1)*9 + s]);
            bw2[s][kc][1] = packh2(w2[(qr*32 + 16*kc + 8 + 2*icb)*9 + s],
                                   w2[(qr*32 + 16*kc + 8 + 2*icb + 1)*9 + s]);
        }

    for (int t = wid; t < 32; t += 8) {
        int oy = t >> 1;
        int ox0 = (t & 1)*16 + qr, ox1 = ox0 + 8;
        float acc[4] = {};
        #pragma unroll
        for (int ky = 0; ky < 3; ky++) {
            #pragma unroll
            for (int kx = 0; kx < 3; kx++) {
                int r0 = (oy + ky)*MID_W + ox0 + kx;
                int r1 = (oy + ky)*MID_W + ox1 + kx;
                int s = ky*3 + kx;
                #pragma unroll
                for (int kc = 0; kc < 2; kc++) {
                    unsigned a[4];
                    a[0] = sMid[(8*kc + icb)*PMID     + r0];
                    a[1] = sMid[(8*kc + icb)*PMID     + r1];
                    a[2] = sMid[(8*kc + 4 + icb)*PMID + r0];
                    a[3] = sMid[(8*kc + 4 + icb)*PMID + r1];
                    mma_f16_k16(acc, a, bw2[s][kc]);
                }
            }
        }
        int oc = 2*icb;
        float bb0 = sB2[oc], bb1 = sB2[oc+1];
        float svA = sVal[ox0], svB = sVal[ox1];
        float r0 = fmaxf(acc[0] + bb0, 0.f);
        float r1 = fmaxf(acc[1] + bb1, 0.f);
        float r2 = fmaxf(acc[2] + bb0, 0.f);
        float r3 = fmaxf(acc[3] + bb1, 0.f);
        float s0 = r0*svA + r2*svB;
        float s1 = r1*svA + r3*svB;
        #pragma unroll
        for (int m = 4; m <= 16; m <<= 1) {
            s0 += __shfl_xor_sync(0xFFFFFFFFu, s0, m);
            s1 += __shfl_xor_sync(0xFFFFFFFFu, s1, m);
        }
        int y = Y0 + oy;
        if (qr == 0 && y < Pn) {
            int xp = blockIdx.x*2 + (t & 1);
            g_PART[((size_t)(n*Hn + oc    )*Pn + y)*64 + xp] = s0;
            g_PART[((size_t)(n*Hn + oc + 1)*Pn + y)*64 + xp] = s1;
        }
    }
}

// ============================================================
// K6: reduce partials -> out[b,p] = mean_h sum_xp
// ============================================================
__global__ __launch_bounds__(128) void reduce_kernel(float* __restrict__ out)
{
    const int bp = blockIdx.x;
    const int b = bp / Pn, p = bp % Pn;
    const int tid = threadIdx.x;
    float s = 0.f;
    for (int i = tid; i < 512; i += 128) {
        int h = i >> 6, xp = i & 63;
        if (xp < 58)
            s += g_PART[((size_t)(b*Hn + h)*Pn + p)*64 + xp];
    }
    __shared__ float red[128];
    red[tid] = s; __syncthreads();
    for (int st = 64; st > 0; st >>= 1) {
        if (tid < st) red[tid] += red[tid + st];
        __syncthreads();
    }
    if (tid == 0) out[bp] = red[0] * 0.125f;
}

// ============================================================
extern "C" void kernel_launch(void* const* d_in, const int* in_sizes, int n_in,
                              void* d_out, int out_size)
{
    const float* query = (const float*)d_in[0];
    const float* key_t = (const float*)d_in[1];
    const float* value = (const float*)d_in[2];
    const float* Wq    = (const float*)d_in[3];
    const float* bq    = (const float*)d_in[4];
    const float* Wk    = (const float*)d_in[5];
    const float* bk    = (const float*)d_in[6];
    const float* c1w   = (const float*)d_in[7];
    const float* c1b   = (const float*)d_in[8];
    const float* c2w   = (const float*)d_in[9];
    const float* c2b   = (const float*)d_in[10];
    float* out = (float*)d_out;

    static int smem_set = 0;
    if (!smem_set) {
        cudaFuncSetAttribute(fused_conv_kernel,
                             cudaFuncAttributeMaxDynamicSharedMemorySize, SMEM_FUSED);
        smem_set = 1;
    }

    proj_kernel<<<dim3(8, 57, 2), 256>>>(query, key_t, Wq, bq, Wk, bk);
    scores_kernel<<<dim3(15, 15, 32), 256>>>();
    modsm_kernel<<<dim3(113, 16), 256>>>();
    fused_conv_kernel<<<dim3(29, 57, 4), 256, SMEM_FUSED>>>(c1w, c1b, c2w, c2b, value);
    reduce_kernel<<<dim3(Bn*Pn), 128>>>(out);
}